// round 3
// baseline (speedup 1.0000x reference)
#include <cuda_runtime.h>
#include <math.h>

// Problem constants
#define BB   2
#define SS   2048
#define DD   1024
#define HH   16
#define DKK  64
#define MM   (BB*SS)   // 4096

// Scratch buffers (device globals — no allocation allowed)
__device__ float g_q[MM*DD];
__device__ float g_k[MM*DD];
__device__ float g_v[MM*DD];
__device__ float g_att[MM*DD];

// ---------------------------------------------------------------------------
// GEMM: C[M,N] = A[M,K] @ B[N,K]^T + bias[N]
// Tiles: BM=128, BN=128, BK=16, 256 threads, 8x8 per thread (strided mapping).
// ---------------------------------------------------------------------------
__global__ __launch_bounds__(256) void gemm_nt_bias(
    const float* __restrict__ A, const float* __restrict__ B,
    const float* __restrict__ bias, float* __restrict__ C,
    int M, int N, int K)
{
    const int BM = 128, BN = 128, BK = 16;
    __shared__ float As[BK][BM + 4];
    __shared__ float Bs[BK][BN + 4];

    int tid = threadIdx.x;
    int tx = tid & 15;        // 0..15 -> cols tx + 16*j
    int ty = tid >> 4;        // 0..15 -> rows ty + 16*i
    int bm = blockIdx.y * BM;
    int bn = blockIdx.x * BN;

    float acc[8][8];
#pragma unroll
    for (int i = 0; i < 8; i++)
#pragma unroll
        for (int j = 0; j < 8; j++) acc[i][j] = 0.f;

    int lr = tid >> 2;          // 0..63 (two rows: lr, lr+64)
    int lc = (tid & 3) * 4;     // 0,4,8,12

    const float* Ap = A + (size_t)(bm + lr) * K + lc;
    const float* Bp = B + (size_t)(bn + lr) * K + lc;

    for (int k0 = 0; k0 < K; k0 += BK) {
#pragma unroll
        for (int r = 0; r < 2; r++) {
            float4 va = *(const float4*)(Ap + (size_t)r * 64 * K + k0);
            As[lc + 0][lr + r * 64] = va.x;
            As[lc + 1][lr + r * 64] = va.y;
            As[lc + 2][lr + r * 64] = va.z;
            As[lc + 3][lr + r * 64] = va.w;
            float4 vb = *(const float4*)(Bp + (size_t)r * 64 * K + k0);
            Bs[lc + 0][lr + r * 64] = vb.x;
            Bs[lc + 1][lr + r * 64] = vb.y;
            Bs[lc + 2][lr + r * 64] = vb.z;
            Bs[lc + 3][lr + r * 64] = vb.w;
        }
        __syncthreads();
#pragma unroll
        for (int k = 0; k < BK; k++) {
            float a[8], b[8];
#pragma unroll
            for (int i = 0; i < 8; i++) a[i] = As[k][ty + i * 16];
#pragma unroll
            for (int j = 0; j < 8; j++) b[j] = Bs[k][tx + j * 16];
#pragma unroll
            for (int i = 0; i < 8; i++)
#pragma unroll
                for (int j = 0; j < 8; j++)
                    acc[i][j] = fmaf(a[i], b[j], acc[i][j]);
        }
        __syncthreads();
    }

#pragma unroll
    for (int j = 0; j < 8; j++) {
        float bv = bias[bn + tx + j * 16];
#pragma unroll
        for (int i = 0; i < 8; i++)
            C[(size_t)(bm + ty + i * 16) * N + bn + tx + j * 16] = acc[i][j] + bv;
    }
}

// ---------------------------------------------------------------------------
// Flash attention (fp32, causal). One CTA per (q-block of 64, head, batch).
// Q tile 64x64 in smem; K/V chunks of 32 rows; S tile 64x32.
// Static shared memory only (~42.5 KB) — no dynamic smem, no FuncSetAttribute.
// ---------------------------------------------------------------------------
#define AQ    64
#define AKC   32          // k-chunk rows
#define QSTR  65          // Q/K/V row stride (padded)
#define SSTR  33          // S tile row stride (padded)

__global__ __launch_bounds__(256) void attn_kernel(
    const float* __restrict__ Q, const float* __restrict__ K,
    const float* __restrict__ V, float* __restrict__ O)
{
    __shared__ float sQ[AQ  * QSTR];   // 64 x 64 (+pad)
    __shared__ float sK[AKC * QSTR];   // 32 x 64 (+pad)
    __shared__ float sV[AKC * QSTR];   // 32 x 64 (+pad)
    __shared__ float sS[AQ  * SSTR];   // 64 x 32 (+pad)
    __shared__ float sM[AQ], sL[AQ], sA[AQ];

    int tid = threadIdx.x;
    int tx = tid & 15;   // col group: cols tx + 16*j
    int ty = tid >> 4;   // row group: rows ty + 16*i
    int qblk = blockIdx.x;      // 0..31
    int h    = blockIdx.y;
    int b    = blockIdx.z;
    int qbase = qblk * AQ;

    const float* Qb = Q + (size_t)b * SS * DD + h * DKK;
    const float* Kb = K + (size_t)b * SS * DD + h * DKK;
    const float* Vb = V + (size_t)b * SS * DD + h * DKK;

    // Load Q tile: 64 rows x 64 cols
    {
        int r = tid >> 4;
        int c = (tid & 15) * 4;
#pragma unroll
        for (int it = 0; it < 4; it++) {
            int row = r + it * 16;
            float4 v = *(const float4*)(Qb + (size_t)(qbase + row) * DD + c);
            sQ[row * QSTR + c + 0] = v.x;
            sQ[row * QSTR + c + 1] = v.y;
            sQ[row * QSTR + c + 2] = v.z;
            sQ[row * QSTR + c + 3] = v.w;
        }
    }
    if (tid < AQ) { sM[tid] = -INFINITY; sL[tid] = 0.f; }

    float o[4][4];
#pragma unroll
    for (int i = 0; i < 4; i++)
#pragma unroll
        for (int j = 0; j < 4; j++) o[i][j] = 0.f;

    const int nkc = 2 * (qblk + 1);   // causal: 32-row chunks up to q-block end
    for (int kc = 0; kc < nkc; kc++) {
        int kbase = kc * AKC;

        // Load K chunk: 32 rows x 64 cols (256 threads -> 2 float4 each)
        {
            int r = tid >> 4;            // 0..15
            int c = (tid & 15) * 4;
#pragma unroll
            for (int it = 0; it < 2; it++) {
                int row = r + it * 16;
                float4 v = *(const float4*)(Kb + (size_t)(kbase + row) * DD + c);
                sK[row * QSTR + c + 0] = v.x;
                sK[row * QSTR + c + 1] = v.y;
                sK[row * QSTR + c + 2] = v.z;
                sK[row * QSTR + c + 3] = v.w;
            }
        }
        __syncthreads();

        // S = Q @ K^T * (1/sqrt(dk)) : 64x32 tile, 4x2 per thread
        float s[4][2];
#pragma unroll
        for (int i = 0; i < 4; i++)
#pragma unroll
            for (int j = 0; j < 2; j++) s[i][j] = 0.f;

#pragma unroll
        for (int d = 0; d < 64; d++) {
            float a[4], bb[2];
#pragma unroll
            for (int i = 0; i < 4; i++) a[i] = sQ[(ty + i * 16) * QSTR + d];
#pragma unroll
            for (int j = 0; j < 2; j++) bb[j] = sK[(tx + j * 16) * QSTR + d];
#pragma unroll
            for (int i = 0; i < 4; i++)
#pragma unroll
                for (int j = 0; j < 2; j++)
                    s[i][j] = fmaf(a[i], bb[j], s[i][j]);
        }

        bool diag = (kc >= 2 * qblk);   // chunk overlaps the diagonal block
#pragma unroll
        for (int i = 0; i < 4; i++) {
            int grow = qbase + ty + i * 16;
#pragma unroll
            for (int j = 0; j < 2; j++) {
                int gcol = kbase + tx + j * 16;
                float val = s[i][j] * 0.125f;   // 1/sqrt(64)
                if (diag && gcol > grow) val = -INFINITY;
                sS[(ty + i * 16) * SSTR + tx + j * 16] = val;
            }
        }
        __syncthreads();

        // Load V chunk while 64 threads do softmax row update
        {
            int r = tid >> 4;
            int c = (tid & 15) * 4;
#pragma unroll
            for (int it = 0; it < 2; it++) {
                int row = r + it * 16;
                float4 v = *(const float4*)(Vb + (size_t)(kbase + row) * DD + c);
                sV[row * QSTR + c + 0] = v.x;
                sV[row * QSTR + c + 1] = v.y;
                sV[row * QSTR + c + 2] = v.z;
                sV[row * QSTR + c + 3] = v.w;
            }
        }
        if (tid < AQ) {
            float* rp = sS + tid * SSTR;
            float mold = sM[tid];
            float mx = mold;
#pragma unroll
            for (int c = 0; c < AKC; c++) mx = fmaxf(mx, rp[c]);
            float alpha = __expf(mold - mx);   // 0 when mold = -inf
            float sum = 0.f;
#pragma unroll
            for (int c = 0; c < AKC; c++) {
                float p = __expf(rp[c] - mx);
                rp[c] = p;
                sum += p;
            }
            sM[tid] = mx;
            sL[tid] = sL[tid] * alpha + sum;
            sA[tid] = alpha;
        }
        __syncthreads();

        // O = O*alpha + P @ V
        float al[4];
#pragma unroll
        for (int i = 0; i < 4; i++) al[i] = sA[ty + i * 16];
#pragma unroll
        for (int i = 0; i < 4; i++)
#pragma unroll
            for (int j = 0; j < 4; j++) o[i][j] *= al[i];

#pragma unroll
        for (int kk = 0; kk < AKC; kk++) {
            float p[4], vv[4];
#pragma unroll
            for (int i = 0; i < 4; i++) p[i] = sS[(ty + i * 16) * SSTR + kk];
#pragma unroll
            for (int j = 0; j < 4; j++) vv[j] = sV[kk * QSTR + tx + j * 16];
#pragma unroll
            for (int i = 0; i < 4; i++)
#pragma unroll
                for (int j = 0; j < 4; j++)
                    o[i][j] = fmaf(p[i], vv[j], o[i][j]);
        }
        __syncthreads();
    }

    // Final normalize + store (output layout [B,S,D] with head slice at h*64)
    float linv[4];
#pragma unroll
    for (int i = 0; i < 4; i++) linv[i] = 1.0f / sL[ty + i * 16];
#pragma unroll
    for (int i = 0; i < 4; i++) {
        int grow = qbase + ty + i * 16;
#pragma unroll
        for (int j = 0; j < 4; j++) {
            O[((size_t)b * SS + grow) * DD + h * DKK + tx + j * 16] =
                o[i][j] * linv[i];
        }
    }
}

// ---------------------------------------------------------------------------
// Launch
// ---------------------------------------------------------------------------
extern "C" void kernel_launch(void* const* d_in, const int* in_sizes, int n_in,
                              void* d_out, int out_size)
{
    const float* q  = (const float*)d_in[0];
    const float* k  = (const float*)d_in[1];
    const float* v  = (const float*)d_in[2];
    const float* Wq = (const float*)d_in[3];
    const float* bq = (const float*)d_in[4];
    const float* Wk = (const float*)d_in[5];
    const float* bk = (const float*)d_in[6];
    const float* Wv = (const float*)d_in[7];
    const float* bv = (const float*)d_in[8];
    const float* Wo = (const float*)d_in[9];
    const float* bo = (const float*)d_in[10];
    float* out = (float*)d_out;

    float *gq, *gk, *gv, *ga;
    cudaGetSymbolAddress((void**)&gq, g_q);
    cudaGetSymbolAddress((void**)&gk, g_k);
    cudaGetSymbolAddress((void**)&gv, g_v);
    cudaGetSymbolAddress((void**)&ga, g_att);

    dim3 gemm_grid(DD / 128, MM / 128);   // (8, 32)

    gemm_nt_bias<<<gemm_grid, 256>>>(q, Wq, bq, gq, MM, DD, DD);
    gemm_nt_bias<<<gemm_grid, 256>>>(k, Wk, bk, gk, MM, DD, DD);
    gemm_nt_bias<<<gemm_grid, 256>>>(v, Wv, bv, gv, MM, DD, DD);

    attn_kernel<<<dim3(SS / AQ, HH, BB), 256>>>(gq, gk, gv, ga);

    gemm_nt_bias<<<gemm_grid, 256>>>(ga, Wo, bo, out, MM, DD, DD);
}

// round 7
// speedup vs baseline: 1.1298x; 1.1298x over previous
#include <cuda_runtime.h>
#include <math.h>
#include <stdint.h>

typedef unsigned long long ull;

// Problem constants
#define BB   2
#define SS   2048
#define DD   1024
#define HH   16
#define DKK  64
#define MM   (BB*SS)   // 4096

// Scratch buffers (device globals — no allocation allowed)
__device__ float g_q[MM*DD];
__device__ float g_k[MM*DD];
__device__ float g_v[MM*DD];
__device__ float g_att[MM*DD];

// ---------------------------------------------------------------------------
// Packed f32x2 helpers (Blackwell 2x fp32 path)
// ---------------------------------------------------------------------------
__device__ __forceinline__ ull fma2(ull a, ull b, ull c) {
    ull d;
    asm("fma.rn.f32x2 %0, %1, %2, %3;" : "=l"(d) : "l"(a), "l"(b), "l"(c));
    return d;
}
__device__ __forceinline__ ull mul2(ull a, ull b) {
    ull d;
    asm("mul.rn.f32x2 %0, %1, %2;" : "=l"(d) : "l"(a), "l"(b));
    return d;
}
__device__ __forceinline__ ull pack2(float lo, float hi) {
    ull r;
    asm("mov.b64 %0, {%1, %2};" : "=l"(r) : "f"(lo), "f"(hi));
    return r;
}
__device__ __forceinline__ void unpack2(ull v, float& lo, float& hi) {
    asm("mov.b64 {%0, %1}, %2;" : "=f"(lo), "=f"(hi) : "l"(v));
}

// ---------------------------------------------------------------------------
// GEMM: C[M,N] = A[M,K] @ B[N,K]^T + bias[N], packed fp32x2 over k-pairs.
// Tile 128x128, BK=32, 512 threads, 8x4 outputs/thread, acc packed (k even/odd).
// Smem row-major [m][k] stride 34: even float stride (8B-aligned pairs),
// odd 8B-word stride (17) -> conflict-free LDS.64 across lanes.
// ---------------------------------------------------------------------------
#define GBK   32
#define GSTR  34

__global__ __launch_bounds__(512) void gemm_f32x2(
    const float* __restrict__ A, const float* __restrict__ B,
    const float* __restrict__ bias, float* __restrict__ C)
{
    __shared__ float As[128 * GSTR];
    __shared__ float Bs[128 * GSTR];

    int tid = threadIdx.x;
    int tx = tid & 31;        // col slot: cols tx + j*32
    int ty = tid >> 5;        // row slot: rows ty + i*16
    int bn = blockIdx.x * 128, bm = blockIdx.y * 128;

    ull acc[8][4];
#pragma unroll
    for (int i = 0; i < 8; i++)
#pragma unroll
        for (int j = 0; j < 4; j++) acc[i][j] = 0ULL;

    for (int k0 = 0; k0 < DD; k0 += GBK) {
        // Load A/B tiles: 128 rows x 32 floats each (1024 float4 per tile)
#pragma unroll
        for (int u = 0; u < 2; u++) {
            int idx = tid + u * 512;
            int row = idx >> 3, c = (idx & 7) * 4;
            float4 va = *(const float4*)(A + (size_t)(bm + row) * DD + k0 + c);
            *(float2*)&As[row * GSTR + c]     = make_float2(va.x, va.y);
            *(float2*)&As[row * GSTR + c + 2] = make_float2(va.z, va.w);
            float4 vb = *(const float4*)(B + (size_t)(bn + row) * DD + k0 + c);
            *(float2*)&Bs[row * GSTR + c]     = make_float2(vb.x, vb.y);
            *(float2*)&Bs[row * GSTR + c + 2] = make_float2(vb.z, vb.w);
        }
        __syncthreads();

#pragma unroll
        for (int kp = 0; kp < GBK / 2; kp++) {
            ull a2[8], b2[4];
#pragma unroll
            for (int i = 0; i < 8; i++)
                a2[i] = *(const ull*)&As[(ty + i * 16) * GSTR + kp * 2];
#pragma unroll
            for (int j = 0; j < 4; j++)
                b2[j] = *(const ull*)&Bs[(tx + j * 32) * GSTR + kp * 2];
#pragma unroll
            for (int i = 0; i < 8; i++)
#pragma unroll
                for (int j = 0; j < 4; j++)
                    acc[i][j] = fma2(a2[i], b2[j], acc[i][j]);
        }
        __syncthreads();
    }

    // Epilogue: horizontal add of packed halves + bias
#pragma unroll
    for (int j = 0; j < 4; j++) {
        int col = bn + tx + j * 32;
        float bv = bias[col];
#pragma unroll
        for (int i = 0; i < 8; i++) {
            float lo, hi;
            unpack2(acc[i][j], lo, hi);
            C[(size_t)(bm + ty + i * 16) * DD + col] = lo + hi + bv;
        }
    }
}

// ---------------------------------------------------------------------------
// Flash attention (fp32, causal), f32x2 inner loops.
// One CTA per (q-block 64, head, batch). K/V chunks of 32 rows.
// QK^T packed along d (contiguous pairs both sides); PV packed along columns.
// ---------------------------------------------------------------------------
#define AQ    64
#define AKC   32
#define QSTR  66   // even -> 8B-aligned d-pairs; word stride 33 odd -> no conflicts
#define SSTR  33

__global__ __launch_bounds__(256) void attn_kernel(
    const float* __restrict__ Q, const float* __restrict__ K,
    const float* __restrict__ V, float* __restrict__ O)
{
    __shared__ float sQ[AQ  * QSTR];
    __shared__ float sK[AKC * QSTR];
    __shared__ float sV[AKC * QSTR];
    __shared__ float sS[AQ  * SSTR];
    __shared__ float sM[AQ], sL[AQ], sA[AQ];

    int tid = threadIdx.x;
    int tx = tid & 15;
    int ty = tid >> 4;
    int qblk = blockIdx.x;
    int h    = blockIdx.y;
    int b    = blockIdx.z;
    int qbase = qblk * AQ;

    const float* Qb = Q + (size_t)b * SS * DD + h * DKK;
    const float* Kb = K + (size_t)b * SS * DD + h * DKK;
    const float* Vb = V + (size_t)b * SS * DD + h * DKK;

    // Load Q tile: 64 rows x 64 cols
    {
        int r = tid >> 4;
        int c = (tid & 15) * 4;
#pragma unroll
        for (int it = 0; it < 4; it++) {
            int row = r + it * 16;
            float4 v = *(const float4*)(Qb + (size_t)(qbase + row) * DD + c);
            sQ[row * QSTR + c + 0] = v.x;
            sQ[row * QSTR + c + 1] = v.y;
            sQ[row * QSTR + c + 2] = v.z;
            sQ[row * QSTR + c + 3] = v.w;
        }
    }
    if (tid < AQ) { sM[tid] = -INFINITY; sL[tid] = 0.f; }

    // Output accumulator: 4 rows x 2 col-pairs (cols tx*2 + j*32 {,+1})
    ull o2[4][2];
#pragma unroll
    for (int i = 0; i < 4; i++)
#pragma unroll
        for (int j = 0; j < 2; j++) o2[i][j] = 0ULL;

    const int nkc = 2 * (qblk + 1);
    for (int kc = 0; kc < nkc; kc++) {
        int kbase = kc * AKC;

        // Load K chunk: 32 rows x 64 cols
        {
            int r = tid >> 4;
            int c = (tid & 15) * 4;
#pragma unroll
            for (int it = 0; it < 2; it++) {
                int row = r + it * 16;
                float4 v = *(const float4*)(Kb + (size_t)(kbase + row) * DD + c);
                sK[row * QSTR + c + 0] = v.x;
                sK[row * QSTR + c + 1] = v.y;
                sK[row * QSTR + c + 2] = v.z;
                sK[row * QSTR + c + 3] = v.w;
            }
        }
        __syncthreads();

        // S = Q @ K^T packed over d: s2 accumulates (even-d, odd-d) halves
        ull s2[4][2];
#pragma unroll
        for (int i = 0; i < 4; i++)
#pragma unroll
            for (int j = 0; j < 2; j++) s2[i][j] = 0ULL;

#pragma unroll
        for (int dp = 0; dp < 32; dp++) {
            ull a2[4], b2[2];
#pragma unroll
            for (int i = 0; i < 4; i++)
                a2[i] = *(const ull*)&sQ[(ty + i * 16) * QSTR + dp * 2];
#pragma unroll
            for (int j = 0; j < 2; j++)
                b2[j] = *(const ull*)&sK[(tx + j * 16) * QSTR + dp * 2];
#pragma unroll
            for (int i = 0; i < 4; i++)
#pragma unroll
                for (int j = 0; j < 2; j++)
                    s2[i][j] = fma2(a2[i], b2[j], s2[i][j]);
        }

        bool diag = (kc >= 2 * qblk);
#pragma unroll
        for (int i = 0; i < 4; i++) {
            int grow = qbase + ty + i * 16;
#pragma unroll
            for (int j = 0; j < 2; j++) {
                float lo, hi;
                unpack2(s2[i][j], lo, hi);
                int gcol = kbase + tx + j * 16;
                float val = (lo + hi) * 0.125f;   // 1/sqrt(64)
                if (diag && gcol > grow) val = -INFINITY;
                sS[(ty + i * 16) * SSTR + tx + j * 16] = val;
            }
        }
        __syncthreads();

        // Load V chunk while 64 threads do softmax row update
        {
            int r = tid >> 4;
            int c = (tid & 15) * 4;
#pragma unroll
            for (int it = 0; it < 2; it++) {
                int row = r + it * 16;
                float4 v = *(const float4*)(Vb + (size_t)(kbase + row) * DD + c);
                sV[row * QSTR + c + 0] = v.x;
                sV[row * QSTR + c + 1] = v.y;
                sV[row * QSTR + c + 2] = v.z;
                sV[row * QSTR + c + 3] = v.w;
            }
        }
        if (tid < AQ) {
            float* rp = sS + tid * SSTR;
            float mold = sM[tid];
            float mx = mold;
#pragma unroll
            for (int c = 0; c < AKC; c++) mx = fmaxf(mx, rp[c]);
            float alpha = __expf(mold - mx);
            float sum = 0.f;
#pragma unroll
            for (int c = 0; c < AKC; c++) {
                float p = __expf(rp[c] - mx);
                rp[c] = p;
                sum += p;
            }
            sM[tid] = mx;
            sL[tid] = sL[tid] * alpha + sum;
            sA[tid] = alpha;
        }
        __syncthreads();

        // O = O*alpha + P @ V  (packed along output columns)
#pragma unroll
        for (int i = 0; i < 4; i++) {
            ull al2 = pack2(sA[ty + i * 16], sA[ty + i * 16]);
#pragma unroll
            for (int j = 0; j < 2; j++) o2[i][j] = mul2(o2[i][j], al2);
        }

#pragma unroll
        for (int kk = 0; kk < AKC; kk++) {
            ull pp[4], v2[2];
#pragma unroll
            for (int i = 0; i < 4; i++) {
                float p = sS[(ty + i * 16) * SSTR + kk];
                pp[i] = pack2(p, p);
            }
#pragma unroll
            for (int j = 0; j < 2; j++)
                v2[j] = *(const ull*)&sV[kk * QSTR + tx * 2 + j * 32];
#pragma unroll
            for (int i = 0; i < 4; i++)
#pragma unroll
                for (int j = 0; j < 2; j++)
                    o2[i][j] = fma2(pp[i], v2[j], o2[i][j]);
        }
        __syncthreads();
    }

    // Final normalize + store (cols tx*2 + j*32, aligned float2 stores)
#pragma unroll
    for (int i = 0; i < 4; i++) {
        int grow = qbase + ty + i * 16;
        float linv = 1.0f / sL[ty + i * 16];
#pragma unroll
        for (int j = 0; j < 2; j++) {
            float lo, hi;
            unpack2(o2[i][j], lo, hi);
            float2 ov = make_float2(lo * linv, hi * linv);
            *(float2*)(O + ((size_t)b * SS + grow) * DD + h * DKK
                        + tx * 2 + j * 32) = ov;
        }
    }
}

// ---------------------------------------------------------------------------
// Launch
// ---------------------------------------------------------------------------
extern "C" void kernel_launch(void* const* d_in, const int* in_sizes, int n_in,
                              void* d_out, int out_size)
{
    const float* q  = (const float*)d_in[0];
    const float* k  = (const float*)d_in[1];
    const float* v  = (const float*)d_in[2];
    const float* Wq = (const float*)d_in[3];
    const float* bq = (const float*)d_in[4];
    const float* Wk = (const float*)d_in[5];
    const float* bk = (const float*)d_in[6];
    const float* Wv = (const float*)d_in[7];
    const float* bv = (const float*)d_in[8];
    const float* Wo = (const float*)d_in[9];
    const float* bo = (const float*)d_in[10];
    float* out = (float*)d_out;

    float *gq, *gk, *gv, *ga;
    cudaGetSymbolAddress((void**)&gq, g_q);
    cudaGetSymbolAddress((void**)&gk, g_k);
    cudaGetSymbolAddress((void**)&gv, g_v);
    cudaGetSymbolAddress((void**)&ga, g_att);

    dim3 gemm_grid(DD / 128, MM / 128);   // (8, 32)

    gemm_f32x2<<<gemm_grid, 512>>>(q, Wq, bq, gq);
    gemm_f32x2<<<gemm_grid, 512>>>(k, Wk, bk, gk);
    gemm_f32x2<<<gemm_grid, 512>>>(v, Wv, bv, gv);

    attn_kernel<<<dim3(SS / AQ, HH, BB), 256>>>(gq, gk, gv, ga);

    gemm_f32x2<<<gemm_grid, 512>>>(ga, Wo, bo, out);
}

// round 8
// speedup vs baseline: 1.6823x; 1.4891x over previous
#include <cuda_runtime.h>
#include <cuda_bf16.h>
#include <math.h>
#include <stdint.h>

typedef unsigned long long ull;

// Problem constants
#define BB   2
#define SS   2048
#define DD   1024
#define HH   16
#define DKK  64
#define MM   (BB*SS)   // 4096

// Scratch buffers (device globals — no allocation allowed)
__device__ float g_q[MM*DD];
__device__ float g_k[MM*DD];
__device__ float g_v[MM*DD];
__device__ float g_att[MM*DD];
__device__ __nv_bfloat16 g_ah[MM*DD];   // activation hi
__device__ __nv_bfloat16 g_al[MM*DD];   // activation lo
__device__ __nv_bfloat16 g_wh[DD*DD];   // weight hi
__device__ __nv_bfloat16 g_wl[DD*DD];   // weight lo

// ---------------------------------------------------------------------------
// PTX helpers
// ---------------------------------------------------------------------------
__device__ __forceinline__ uint32_t smem_u32(const void* p) {
    uint32_t a;
    asm("{ .reg .u64 t; cvta.to.shared.u64 t, %1; cvt.u32.u64 %0, t; }"
        : "=r"(a) : "l"(p));
    return a;
}

__device__ __forceinline__ void ldm_x4(uint32_t* r, uint32_t addr) {
    asm volatile("ldmatrix.sync.aligned.m8n8.x4.shared.b16 {%0,%1,%2,%3}, [%4];"
                 : "=r"(r[0]), "=r"(r[1]), "=r"(r[2]), "=r"(r[3]) : "r"(addr));
}

__device__ __forceinline__ void mma16816(float* c, const uint32_t* a,
                                         const uint32_t* b) {
    asm volatile(
        "mma.sync.aligned.m16n8k16.row.col.f32.bf16.bf16.f32 "
        "{%0,%1,%2,%3}, {%4,%5,%6,%7}, {%8,%9}, {%0,%1,%2,%3};"
        : "+f"(c[0]), "+f"(c[1]), "+f"(c[2]), "+f"(c[3])
        : "r"(a[0]), "r"(a[1]), "r"(a[2]), "r"(a[3]), "r"(b[0]), "r"(b[1]));
}

// ---------------------------------------------------------------------------
// fp32 -> (bf16 hi, bf16 lo) split conversion
// ---------------------------------------------------------------------------
__global__ __launch_bounds__(256) void cvt_hilo(
    const float* __restrict__ x, __nv_bfloat16* __restrict__ h,
    __nv_bfloat16* __restrict__ l, int n4)
{
    int i = blockIdx.x * blockDim.x + threadIdx.x;
    if (i >= n4) return;
    float4 v = ((const float4*)x)[i];
    __nv_bfloat16 h0 = __float2bfloat16(v.x);
    __nv_bfloat16 h1 = __float2bfloat16(v.y);
    __nv_bfloat16 h2 = __float2bfloat16(v.z);
    __nv_bfloat16 h3 = __float2bfloat16(v.w);
    __nv_bfloat16 l0 = __float2bfloat16(v.x - __bfloat162float(h0));
    __nv_bfloat16 l1 = __float2bfloat16(v.y - __bfloat162float(h1));
    __nv_bfloat16 l2 = __float2bfloat16(v.z - __bfloat162float(h2));
    __nv_bfloat16 l3 = __float2bfloat16(v.w - __bfloat162float(h3));
    ((__nv_bfloat162*)h)[2*i]   = __nv_bfloat162(h0, h1);
    ((__nv_bfloat162*)h)[2*i+1] = __nv_bfloat162(h2, h3);
    ((__nv_bfloat162*)l)[2*i]   = __nv_bfloat162(l0, l1);
    ((__nv_bfloat162*)l)[2*i+1] = __nv_bfloat162(l2, l3);
}

// ---------------------------------------------------------------------------
// mma.sync bf16 hi/lo GEMM: C[M,N] = A[M,K] @ B[N,K]^T + bias
//   C = Ah*Bh + Ah*Bl + Al*Bh  (fp32 accumulators in registers)
// CTA tile 128x128, BK=32, 8 warps (2x4), each warp 64x32 (4x4 m16n8 tiles).
// Smem: bf16 [128][40] per array (80B row stride -> word stride 20, ldmatrix
// conflict-free). Global->register prefetch of chunk t+1 overlaps MMA of t.
// ---------------------------------------------------------------------------
#define GBK  32
#define GNT  (DD / GBK)   // 32 chunks
#define BSTR 40           // bf16 elements per smem row (80 bytes)

__global__ __launch_bounds__(256, 1) void gemm_mma(
    const __nv_bfloat16* __restrict__ AH, const __nv_bfloat16* __restrict__ AL,
    const __nv_bfloat16* __restrict__ BH, const __nv_bfloat16* __restrict__ BL,
    const float* __restrict__ bias, float* __restrict__ C)
{
    __shared__ __align__(16) __nv_bfloat16 sAh[128 * BSTR];
    __shared__ __align__(16) __nv_bfloat16 sAl[128 * BSTR];
    __shared__ __align__(16) __nv_bfloat16 sBh[128 * BSTR];
    __shared__ __align__(16) __nv_bfloat16 sBl[128 * BSTR];

    int tid = threadIdx.x;
    int wid = tid >> 5, lane = tid & 31;
    int wm = wid >> 2;         // 0..1 -> m offset wm*64
    int wn = wid & 3;          // 0..3 -> n offset wn*32
    int bn = blockIdx.x * 128, bm = blockIdx.y * 128;

    uint32_t uAh = smem_u32(sAh), uAl = smem_u32(sAl);
    uint32_t uBh = smem_u32(sBh), uBl = smem_u32(sBl);

    float acc[4][4][4];
#pragma unroll
    for (int mi = 0; mi < 4; mi++)
#pragma unroll
        for (int nj = 0; nj < 4; nj++)
#pragma unroll
            for (int r = 0; r < 4; r++) acc[mi][nj][r] = 0.f;

    // prefetch registers: 8 x uint4 (per thread: 2 slots x 4 arrays)
    uint4 pf[8];
    int ldrow0 = tid >> 2, ldc0 = (tid & 3);            // slot 0: rows 0..63
    int ldrow1 = (tid + 256) >> 2, ldc1 = (tid & 3);    // slot 1: rows 64..127

    auto ldg_chunk = [&](int t) {
        int k0 = t * GBK;
        const __nv_bfloat16* a0 = AH + (size_t)(bm + ldrow0) * DD + k0 + ldc0 * 8;
        const __nv_bfloat16* a1 = AL + (size_t)(bm + ldrow0) * DD + k0 + ldc0 * 8;
        const __nv_bfloat16* b0 = BH + (size_t)(bn + ldrow0) * DD + k0 + ldc0 * 8;
        const __nv_bfloat16* b1 = BL + (size_t)(bn + ldrow0) * DD + k0 + ldc0 * 8;
        pf[0] = *(const uint4*)a0;
        pf[1] = *(const uint4*)a1;
        pf[2] = *(const uint4*)b0;
        pf[3] = *(const uint4*)b1;
        size_t d = (size_t)(ldrow1 - ldrow0) * DD;
        pf[4] = *(const uint4*)(a0 + d);
        pf[5] = *(const uint4*)(a1 + d);
        pf[6] = *(const uint4*)(b0 + d);
        pf[7] = *(const uint4*)(b1 + d);
    };
    auto sts_chunk = [&]() {
        *(uint4*)(sAh + ldrow0 * BSTR + ldc0 * 8) = pf[0];
        *(uint4*)(sAl + ldrow0 * BSTR + ldc0 * 8) = pf[1];
        *(uint4*)(sBh + ldrow0 * BSTR + ldc0 * 8) = pf[2];
        *(uint4*)(sBl + ldrow0 * BSTR + ldc0 * 8) = pf[3];
        *(uint4*)(sAh + ldrow1 * BSTR + ldc1 * 8) = pf[4];
        *(uint4*)(sAl + ldrow1 * BSTR + ldc1 * 8) = pf[5];
        *(uint4*)(sBh + ldrow1 * BSTR + ldc1 * 8) = pf[6];
        *(uint4*)(sBl + ldrow1 * BSTR + ldc1 * 8) = pf[7];
    };

    int q = lane >> 3;              // ldmatrix sub-matrix index
    int lr = lane & 7;

    ldg_chunk(0);
    for (int t = 0; t < GNT; t++) {
        sts_chunk();
        __syncthreads();
        if (t + 1 < GNT) ldg_chunk(t + 1);

#pragma unroll
        for (int kk = 0; kk < 2; kk++) {
            uint32_t ah[16], al[16], bh[8], bl[8];
            // A fragments: 4 m-tiles; sub-matrix q: row += (q&1)*8, k += (q>>1)*8
            {
                int arow = wm * 64 + (q & 1) * 8 + lr;
                int akof = kk * 16 + (q >> 1) * 8;
                uint32_t off = (uint32_t)(arow * BSTR + akof) * 2;
#pragma unroll
                for (int mi = 0; mi < 4; mi++) {
                    ldm_x4(&ah[mi * 4], uAh + off + mi * 16 * BSTR * 2);
                    ldm_x4(&al[mi * 4], uAl + off + mi * 16 * BSTR * 2);
                }
            }
            // B fragments: 2 ldmatrix.x4, each covers 2 n-tiles
            // sub-matrix q: n += (q>>1)*8, k += (q&1)*8
            {
                int brow = wn * 32 + (q >> 1) * 8 + lr;
                int bkof = kk * 16 + (q & 1) * 8;
                uint32_t off = (uint32_t)(brow * BSTR + bkof) * 2;
#pragma unroll
                for (int pj = 0; pj < 2; pj++) {
                    ldm_x4(&bh[pj * 4], uBh + off + pj * 16 * BSTR * 2);
                    ldm_x4(&bl[pj * 4], uBl + off + pj * 16 * BSTR * 2);
                }
            }
#pragma unroll
            for (int mi = 0; mi < 4; mi++)
#pragma unroll
                for (int nj = 0; nj < 4; nj++) {
                    mma16816(acc[mi][nj], &ah[mi * 4], &bh[nj * 2]);
                    mma16816(acc[mi][nj], &ah[mi * 4], &bl[nj * 2]);
                    mma16816(acc[mi][nj], &al[mi * 4], &bh[nj * 2]);
                }
        }
        __syncthreads();
    }

    // Epilogue: fragment layout c0,c1 = (row g, col tg*2 .. +1); c2,c3 = row g+8
    int g = lane >> 2, tg = lane & 3;
#pragma unroll
    for (int mi = 0; mi < 4; mi++) {
#pragma unroll
        for (int nj = 0; nj < 4; nj++) {
            int row = bm + wm * 64 + mi * 16 + g;
            int col = bn + wn * 32 + nj * 8 + tg * 2;
            float b0 = bias[col], b1 = bias[col + 1];
            float2 v0 = make_float2(acc[mi][nj][0] + b0, acc[mi][nj][1] + b1);
            float2 v1 = make_float2(acc[mi][nj][2] + b0, acc[mi][nj][3] + b1);
            *(float2*)(C + (size_t)row * DD + col) = v0;
            *(float2*)(C + (size_t)(row + 8) * DD + col) = v1;
        }
    }
}

// ---------------------------------------------------------------------------
// Flash attention (fp32, causal), f32x2 inner loops — unchanged (passing,
// 762us measured in round 7).
// ---------------------------------------------------------------------------
__device__ __forceinline__ ull fma2(ull a, ull b, ull c) {
    ull d;
    asm("fma.rn.f32x2 %0, %1, %2, %3;" : "=l"(d) : "l"(a), "l"(b), "l"(c));
    return d;
}
__device__ __forceinline__ ull mul2(ull a, ull b) {
    ull d;
    asm("mul.rn.f32x2 %0, %1, %2;" : "=l"(d) : "l"(a), "l"(b));
    return d;
}
__device__ __forceinline__ ull pack2(float lo, float hi) {
    ull r;
    asm("mov.b64 %0, {%1, %2};" : "=l"(r) : "f"(lo), "f"(hi));
    return r;
}
__device__ __forceinline__ void unpack2(ull v, float& lo, float& hi) {
    asm("mov.b64 {%0, %1}, %2;" : "=f"(lo), "=f"(hi) : "l"(v));
}

#define AQ    64
#define AKC   32
#define QSTR  66
#define SSTR  33

__global__ __launch_bounds__(256) void attn_kernel(
    const float* __restrict__ Q, const float* __restrict__ K,
    const float* __restrict__ V, float* __restrict__ O)
{
    __shared__ float sQ[AQ  * QSTR];
    __shared__ float sK[AKC * QSTR];
    __shared__ float sV[AKC * QSTR];
    __shared__ float sS[AQ  * SSTR];
    __shared__ float sM[AQ], sL[AQ], sA[AQ];

    int tid = threadIdx.x;
    int tx = tid & 15;
    int ty = tid >> 4;
    int qblk = blockIdx.x;
    int h    = blockIdx.y;
    int b    = blockIdx.z;
    int qbase = qblk * AQ;

    const float* Qb = Q + (size_t)b * SS * DD + h * DKK;
    const float* Kb = K + (size_t)b * SS * DD + h * DKK;
    const float* Vb = V + (size_t)b * SS * DD + h * DKK;

    {
        int r = tid >> 4;
        int c = (tid & 15) * 4;
#pragma unroll
        for (int it = 0; it < 4; it++) {
            int row = r + it * 16;
            float4 v = *(const float4*)(Qb + (size_t)(qbase + row) * DD + c);
            sQ[row * QSTR + c + 0] = v.x;
            sQ[row * QSTR + c + 1] = v.y;
            sQ[row * QSTR + c + 2] = v.z;
            sQ[row * QSTR + c + 3] = v.w;
        }
    }
    if (tid < AQ) { sM[tid] = -INFINITY; sL[tid] = 0.f; }

    ull o2[4][2];
#pragma unroll
    for (int i = 0; i < 4; i++)
#pragma unroll
        for (int j = 0; j < 2; j++) o2[i][j] = 0ULL;

    const int nkc = 2 * (qblk + 1);
    for (int kc = 0; kc < nkc; kc++) {
        int kbase = kc * AKC;
        {
            int r = tid >> 4;
            int c = (tid & 15) * 4;
#pragma unroll
            for (int it = 0; it < 2; it++) {
                int row = r + it * 16;
                float4 v = *(const float4*)(Kb + (size_t)(kbase + row) * DD + c);
                sK[row * QSTR + c + 0] = v.x;
                sK[row * QSTR + c + 1] = v.y;
                sK[row * QSTR + c + 2] = v.z;
                sK[row * QSTR + c + 3] = v.w;
            }
        }
        __syncthreads();

        ull s2[4][2];
#pragma unroll
        for (int i = 0; i < 4; i++)
#pragma unroll
            for (int j = 0; j < 2; j++) s2[i][j] = 0ULL;

#pragma unroll
        for (int dp = 0; dp < 32; dp++) {
            ull a2[4], b2[2];
#pragma unroll
            for (int i = 0; i < 4; i++)
                a2[i] = *(const ull*)&sQ[(ty + i * 16) * QSTR + dp * 2];
#pragma unroll
            for (int j = 0; j < 2; j++)
                b2[j] = *(const ull*)&sK[(tx + j * 16) * QSTR + dp * 2];
#pragma unroll
            for (int i = 0; i < 4; i++)
#pragma unroll
                for (int j = 0; j < 2; j++)
                    s2[i][j] = fma2(a2[i], b2[j], s2[i][j]);
        }

        bool diag = (kc >= 2 * qblk);
#pragma unroll
        for (int i = 0; i < 4; i++) {
            int grow = qbase + ty + i * 16;
#pragma unroll
            for (int j = 0; j < 2; j++) {
                float lo, hi;
                unpack2(s2[i][j], lo, hi);
                int gcol = kbase + tx + j * 16;
                float val = (lo + hi) * 0.125f;
                if (diag && gcol > grow) val = -INFINITY;
                sS[(ty + i * 16) * SSTR + tx + j * 16] = val;
            }
        }
        __syncthreads();

        {
            int r = tid >> 4;
            int c = (tid & 15) * 4;
#pragma unroll
            for (int it = 0; it < 2; it++) {
                int row = r + it * 16;
                float4 v = *(const float4*)(Vb + (size_t)(kbase + row) * DD + c);
                sV[row * QSTR + c + 0] = v.x;
                sV[row * QSTR + c + 1] = v.y;
                sV[row * QSTR + c + 2] = v.z;
                sV[row * QSTR + c + 3] = v.w;
            }
        }
        if (tid < AQ) {
            float* rp = sS + tid * SSTR;
            float mold = sM[tid];
            float mx = mold;
#pragma unroll
            for (int c = 0; c < AKC; c++) mx = fmaxf(mx, rp[c]);
            float alpha = __expf(mold - mx);
            float sum = 0.f;
#pragma unroll
            for (int c = 0; c < AKC; c++) {
                float p = __expf(rp[c] - mx);
                rp[c] = p;
                sum += p;
            }
            sM[tid] = mx;
            sL[tid] = sL[tid] * alpha + sum;
            sA[tid] = alpha;
        }
        __syncthreads();

#pragma unroll
        for (int i = 0; i < 4; i++) {
            ull al2 = pack2(sA[ty + i * 16], sA[ty + i * 16]);
#pragma unroll
            for (int j = 0; j < 2; j++) o2[i][j] = mul2(o2[i][j], al2);
        }

#pragma unroll
        for (int kk = 0; kk < AKC; kk++) {
            ull pp[4], v2[2];
#pragma unroll
            for (int i = 0; i < 4; i++) {
                float p = sS[(ty + i * 16) * SSTR + kk];
                pp[i] = pack2(p, p);
            }
#pragma unroll
            for (int j = 0; j < 2; j++)
                v2[j] = *(const ull*)&sV[kk * QSTR + tx * 2 + j * 32];
#pragma unroll
            for (int i = 0; i < 4; i++)
#pragma unroll
                for (int j = 0; j < 2; j++)
                    o2[i][j] = fma2(pp[i], v2[j], o2[i][j]);
        }
        __syncthreads();
    }

#pragma unroll
    for (int i = 0; i < 4; i++) {
        int grow = qbase + ty + i * 16;
        float linv = 1.0f / sL[ty + i * 16];
#pragma unroll
        for (int j = 0; j < 2; j++) {
            float lo, hi;
            unpack2(o2[i][j], lo, hi);
            float2 ov = make_float2(lo * linv, hi * linv);
            *(float2*)(O + ((size_t)b * SS + grow) * DD + h * DKK
                        + tx * 2 + j * 32) = ov;
        }
    }
}

// ---------------------------------------------------------------------------
// Launch
// ---------------------------------------------------------------------------
extern "C" void kernel_launch(void* const* d_in, const int* in_sizes, int n_in,
                              void* d_out, int out_size)
{
    const float* q  = (const float*)d_in[0];
    const float* k  = (const float*)d_in[1];
    const float* v  = (const float*)d_in[2];
    const float* Wq = (const float*)d_in[3];
    const float* bq = (const float*)d_in[4];
    const float* Wk = (const float*)d_in[5];
    const float* bk = (const float*)d_in[6];
    const float* Wv = (const float*)d_in[7];
    const float* bv = (const float*)d_in[8];
    const float* Wo = (const float*)d_in[9];
    const float* bo = (const float*)d_in[10];
    float* out = (float*)d_out;

    float *gq, *gk, *gv, *ga;
    __nv_bfloat16 *ah, *al, *wh, *wl;
    cudaGetSymbolAddress((void**)&gq, g_q);
    cudaGetSymbolAddress((void**)&gk, g_k);
    cudaGetSymbolAddress((void**)&gv, g_v);
    cudaGetSymbolAddress((void**)&ga, g_att);
    cudaGetSymbolAddress((void**)&ah, g_ah);
    cudaGetSymbolAddress((void**)&al, g_al);
    cudaGetSymbolAddress((void**)&wh, g_wh);
    cudaGetSymbolAddress((void**)&wl, g_wl);

    const int nA4 = MM * DD / 4;   // 1,048,576
    const int nW4 = DD * DD / 4;   // 262,144
    dim3 tcg(DD / 128, MM / 128);  // (8, 32)

    // Q projection
    cvt_hilo<<<nA4 / 256, 256>>>(q, ah, al, nA4);
    cvt_hilo<<<nW4 / 256, 256>>>(Wq, wh, wl, nW4);
    gemm_mma<<<tcg, 256>>>(ah, al, wh, wl, bq, gq);
    // K projection
    cvt_hilo<<<nA4 / 256, 256>>>(k, ah, al, nA4);
    cvt_hilo<<<nW4 / 256, 256>>>(Wk, wh, wl, nW4);
    gemm_mma<<<tcg, 256>>>(ah, al, wh, wl, bk, gk);
    // V projection
    cvt_hilo<<<nA4 / 256, 256>>>(v, ah, al, nA4);
    cvt_hilo<<<nW4 / 256, 256>>>(Wv, wh, wl, nW4);
    gemm_mma<<<tcg, 256>>>(ah, al, wh, wl, bv, gv);

    // Attention
    attn_kernel<<<dim3(SS / AQ, HH, BB), 256>>>(gq, gk, gv, ga);

    // Output projection
    cvt_hilo<<<nA4 / 256, 256>>>(ga, ah, al, nA4);
    cvt_hilo<<<nW4 / 256, 256>>>(Wo, wh, wl, nW4);
    gemm_mma<<<tcg, 256>>>(ah, al, wh, wl, bo, out);
}

// round 9
// speedup vs baseline: 2.9556x; 1.7569x over previous
#include <cuda_runtime.h>
#include <cuda_bf16.h>
#include <math.h>
#include <stdint.h>

// Problem constants
#define BB   2
#define SS   2048
#define DD   1024
#define HH   16
#define DKK  64
#define MM   (BB*SS)   // 4096

// Scratch buffers (device globals — no allocation allowed)
__device__ float g_q[MM*DD];
__device__ float g_k[MM*DD];
__device__ float g_v[MM*DD];
__device__ float g_att[MM*DD];
__device__ __nv_bfloat16 g_ah[MM*DD];   // activation hi
__device__ __nv_bfloat16 g_al[MM*DD];   // activation lo
__device__ __nv_bfloat16 g_wh[DD*DD];   // weight hi
__device__ __nv_bfloat16 g_wl[DD*DD];   // weight lo

// ---------------------------------------------------------------------------
// PTX helpers
// ---------------------------------------------------------------------------
__device__ __forceinline__ uint32_t smem_u32(const void* p) {
    uint32_t a;
    asm("{ .reg .u64 t; cvta.to.shared.u64 t, %1; cvt.u32.u64 %0, t; }"
        : "=r"(a) : "l"(p));
    return a;
}

__device__ __forceinline__ void ldm_x4(uint32_t* r, uint32_t addr) {
    asm volatile("ldmatrix.sync.aligned.m8n8.x4.shared.b16 {%0,%1,%2,%3}, [%4];"
                 : "=r"(r[0]), "=r"(r[1]), "=r"(r[2]), "=r"(r[3]) : "r"(addr));
}

__device__ __forceinline__ void mma16816(float* c, const uint32_t* a,
                                         const uint32_t* b) {
    asm volatile(
        "mma.sync.aligned.m16n8k16.row.col.f32.bf16.bf16.f32 "
        "{%0,%1,%2,%3}, {%4,%5,%6,%7}, {%8,%9}, {%0,%1,%2,%3};"
        : "+f"(c[0]), "+f"(c[1]), "+f"(c[2]), "+f"(c[3])
        : "r"(a[0]), "r"(a[1]), "r"(a[2]), "r"(a[3]), "r"(b[0]), "r"(b[1]));
}

// pack two floats to bf16x2 (lo = first arg in low 16 bits)
__device__ __forceinline__ uint32_t pk_bf2(float a, float b) {
    __nv_bfloat162 t = __floats2bfloat162_rn(a, b);
    return *reinterpret_cast<uint32_t*>(&t);
}

// split 8 floats into bf16-hi uint4 and bf16-lo uint4
__device__ __forceinline__ void split8(const float* v, uint4& hi, uint4& lo) {
    uint32_t h[4], l[4];
#pragma unroll
    for (int i = 0; i < 4; i++) {
        float a = v[2*i], b = v[2*i+1];
        __nv_bfloat162 hb = __floats2bfloat162_rn(a, b);
        h[i] = *reinterpret_cast<uint32_t*>(&hb);
        float ra = a - __bfloat162float(hb.x);
        float rb = b - __bfloat162float(hb.y);
        __nv_bfloat162 lb = __floats2bfloat162_rn(ra, rb);
        l[i] = *reinterpret_cast<uint32_t*>(&lb);
    }
    hi = make_uint4(h[0], h[1], h[2], h[3]);
    lo = make_uint4(l[0], l[1], l[2], l[3]);
}

// ---------------------------------------------------------------------------
// fp32 -> (bf16 hi, bf16 lo) split conversion
// ---------------------------------------------------------------------------
__global__ __launch_bounds__(256) void cvt_hilo(
    const float* __restrict__ x, __nv_bfloat16* __restrict__ h,
    __nv_bfloat16* __restrict__ l, int n4)
{
    int i = blockIdx.x * blockDim.x + threadIdx.x;
    if (i >= n4) return;
    float4 v = ((const float4*)x)[i];
    __nv_bfloat16 h0 = __float2bfloat16(v.x);
    __nv_bfloat16 h1 = __float2bfloat16(v.y);
    __nv_bfloat16 h2 = __float2bfloat16(v.z);
    __nv_bfloat16 h3 = __float2bfloat16(v.w);
    __nv_bfloat16 l0 = __float2bfloat16(v.x - __bfloat162float(h0));
    __nv_bfloat16 l1 = __float2bfloat16(v.y - __bfloat162float(h1));
    __nv_bfloat16 l2 = __float2bfloat16(v.z - __bfloat162float(h2));
    __nv_bfloat16 l3 = __float2bfloat16(v.w - __bfloat162float(h3));
    ((__nv_bfloat162*)h)[2*i]   = __nv_bfloat162(h0, h1);
    ((__nv_bfloat162*)h)[2*i+1] = __nv_bfloat162(h2, h3);
    ((__nv_bfloat162*)l)[2*i]   = __nv_bfloat162(l0, l1);
    ((__nv_bfloat162*)l)[2*i+1] = __nv_bfloat162(l2, l3);
}

// ---------------------------------------------------------------------------
// mma.sync bf16 hi/lo GEMM (unchanged from round 8, verified).
// ---------------------------------------------------------------------------
#define GBK  32
#define GNT  (DD / GBK)
#define BSTR 40

__global__ __launch_bounds__(256, 1) void gemm_mma(
    const __nv_bfloat16* __restrict__ AH, const __nv_bfloat16* __restrict__ AL,
    const __nv_bfloat16* __restrict__ BH, const __nv_bfloat16* __restrict__ BL,
    const float* __restrict__ bias, float* __restrict__ C)
{
    __shared__ __align__(16) __nv_bfloat16 sAh[128 * BSTR];
    __shared__ __align__(16) __nv_bfloat16 sAl[128 * BSTR];
    __shared__ __align__(16) __nv_bfloat16 sBh[128 * BSTR];
    __shared__ __align__(16) __nv_bfloat16 sBl[128 * BSTR];

    int tid = threadIdx.x;
    int wid = tid >> 5, lane = tid & 31;
    int wm = wid >> 2;
    int wn = wid & 3;
    int bn = blockIdx.x * 128, bm = blockIdx.y * 128;

    uint32_t uAh = smem_u32(sAh), uAl = smem_u32(sAl);
    uint32_t uBh = smem_u32(sBh), uBl = smem_u32(sBl);

    float acc[4][4][4];
#pragma unroll
    for (int mi = 0; mi < 4; mi++)
#pragma unroll
        for (int nj = 0; nj < 4; nj++)
#pragma unroll
            for (int r = 0; r < 4; r++) acc[mi][nj][r] = 0.f;

    uint4 pf[8];
    int ldrow0 = tid >> 2, ldc0 = (tid & 3);
    int ldrow1 = (tid + 256) >> 2, ldc1 = (tid & 3);

    auto ldg_chunk = [&](int t) {
        int k0 = t * GBK;
        const __nv_bfloat16* a0 = AH + (size_t)(bm + ldrow0) * DD + k0 + ldc0 * 8;
        const __nv_bfloat16* a1 = AL + (size_t)(bm + ldrow0) * DD + k0 + ldc0 * 8;
        const __nv_bfloat16* b0 = BH + (size_t)(bn + ldrow0) * DD + k0 + ldc0 * 8;
        const __nv_bfloat16* b1 = BL + (size_t)(bn + ldrow0) * DD + k0 + ldc0 * 8;
        pf[0] = *(const uint4*)a0;
        pf[1] = *(const uint4*)a1;
        pf[2] = *(const uint4*)b0;
        pf[3] = *(const uint4*)b1;
        size_t d = (size_t)(ldrow1 - ldrow0) * DD;
        pf[4] = *(const uint4*)(a0 + d);
        pf[5] = *(const uint4*)(a1 + d);
        pf[6] = *(const uint4*)(b0 + d);
        pf[7] = *(const uint4*)(b1 + d);
    };
    auto sts_chunk = [&]() {
        *(uint4*)(sAh + ldrow0 * BSTR + ldc0 * 8) = pf[0];
        *(uint4*)(sAl + ldrow0 * BSTR + ldc0 * 8) = pf[1];
        *(uint4*)(sBh + ldrow0 * BSTR + ldc0 * 8) = pf[2];
        *(uint4*)(sBl + ldrow0 * BSTR + ldc0 * 8) = pf[3];
        *(uint4*)(sAh + ldrow1 * BSTR + ldc1 * 8) = pf[4];
        *(uint4*)(sAl + ldrow1 * BSTR + ldc1 * 8) = pf[5];
        *(uint4*)(sBh + ldrow1 * BSTR + ldc1 * 8) = pf[6];
        *(uint4*)(sBl + ldrow1 * BSTR + ldc1 * 8) = pf[7];
    };

    int q = lane >> 3;
    int lr = lane & 7;

    ldg_chunk(0);
    for (int t = 0; t < GNT; t++) {
        sts_chunk();
        __syncthreads();
        if (t + 1 < GNT) ldg_chunk(t + 1);

#pragma unroll
        for (int kk = 0; kk < 2; kk++) {
            uint32_t ah[16], al[16], bh[8], bl[8];
            {
                int arow = wm * 64 + (q & 1) * 8 + lr;
                int akof = kk * 16 + (q >> 1) * 8;
                uint32_t off = (uint32_t)(arow * BSTR + akof) * 2;
#pragma unroll
                for (int mi = 0; mi < 4; mi++) {
                    ldm_x4(&ah[mi * 4], uAh + off + mi * 16 * BSTR * 2);
                    ldm_x4(&al[mi * 4], uAl + off + mi * 16 * BSTR * 2);
                }
            }
            {
                int brow = wn * 32 + (q >> 1) * 8 + lr;
                int bkof = kk * 16 + (q & 1) * 8;
                uint32_t off = (uint32_t)(brow * BSTR + bkof) * 2;
#pragma unroll
                for (int pj = 0; pj < 2; pj++) {
                    ldm_x4(&bh[pj * 4], uBh + off + pj * 16 * BSTR * 2);
                    ldm_x4(&bl[pj * 4], uBl + off + pj * 16 * BSTR * 2);
                }
            }
#pragma unroll
            for (int mi = 0; mi < 4; mi++)
#pragma unroll
                for (int nj = 0; nj < 4; nj++) {
                    mma16816(acc[mi][nj], &ah[mi * 4], &bh[nj * 2]);
                    mma16816(acc[mi][nj], &ah[mi * 4], &bl[nj * 2]);
                    mma16816(acc[mi][nj], &al[mi * 4], &bh[nj * 2]);
                }
        }
        __syncthreads();
    }

    int g = lane >> 2, tg = lane & 3;
#pragma unroll
    for (int mi = 0; mi < 4; mi++) {
#pragma unroll
        for (int nj = 0; nj < 4; nj++) {
            int row = bm + wm * 64 + mi * 16 + g;
            int col = bn + wn * 32 + nj * 8 + tg * 2;
            float b0 = bias[col], b1 = bias[col + 1];
            float2 v0 = make_float2(acc[mi][nj][0] + b0, acc[mi][nj][1] + b1);
            float2 v1 = make_float2(acc[mi][nj][2] + b0, acc[mi][nj][3] + b1);
            *(float2*)(C + (size_t)row * DD + col) = v0;
            *(float2*)(C + (size_t)(row + 8) * DD + col) = v1;
        }
    }
}

// ---------------------------------------------------------------------------
// Flash attention with mma.sync bf16 (hi/lo, 3-pass), register online softmax.
// CTA: 128 q-rows x (head, batch). K-chunks of 32. 8 warps x 16 rows.
// Q/K tiles SW128-swizzled [rows][64] bf16; V stored transposed [64 d][32 k]
// at stride 40 (gemm-verified ldmatrix layout). K/V share one smem buffer.
// ---------------------------------------------------------------------------
__global__ __launch_bounds__(256, 1) void attn_mma(
    const float* __restrict__ Q, const float* __restrict__ K,
    const float* __restrict__ V, float* __restrict__ O)
{
    __shared__ __align__(16) __nv_bfloat16 sQh[128 * 64];
    __shared__ __align__(16) __nv_bfloat16 sQl[128 * 64];
    __shared__ __align__(16) char sKV[10240];   // K: hi@0,lo@4096 | V^T: hi@0,lo@5120

    int tid = threadIdx.x;
    int wid = tid >> 5, lane = tid & 31;
    int g = lane >> 2, tg = lane & 3;
    int q = lane >> 3, lr = lane & 7;
    int qblk = (int)gridDim.x - 1 - (int)blockIdx.x;   // heavy blocks first
    int h = blockIdx.y, b = blockIdx.z;
    int qbase = qblk * 128;

    const float* Qb = Q + (size_t)b * SS * DD + h * DKK;
    const float* Kb = K + (size_t)b * SS * DD + h * DKK;
    const float* Vb = V + (size_t)b * SS * DD + h * DKK;

    uint32_t uQh = smem_u32(sQh), uQl = smem_u32(sQl);
    uint32_t uKV = smem_u32(sKV);

    // Load Q tile (x 1/sqrt(dk)), hi/lo split, SW128
#pragma unroll
    for (int it = 0; it < 4; it++) {
        int slot = tid + it * 256;
        int r = slot >> 3, c8 = slot & 7;
        const float* src = Qb + (size_t)(qbase + r) * DD + c8 * 8;
        float4 u = *(const float4*)src;
        float4 v = *(const float4*)(src + 4);
        float vals[8] = {u.x*0.125f, u.y*0.125f, u.z*0.125f, u.w*0.125f,
                         v.x*0.125f, v.y*0.125f, v.z*0.125f, v.w*0.125f};
        uint4 hi, lo;
        split8(vals, hi, lo);
        uint32_t off = (uint32_t)(r * 128 + c8 * 16);
        off ^= (off >> 3) & 0x70;
        *(uint4*)((char*)sQh + off) = hi;
        *(uint4*)((char*)sQl + off) = lo;
    }

    float m0 = -1e30f, m1 = -1e30f, lsum0 = 0.f, lsum1 = 0.f;
    float o[8][4];
#pragma unroll
    for (int d8 = 0; d8 < 8; d8++)
#pragma unroll
        for (int r = 0; r < 4; r++) o[d8][r] = 0.f;

    const int row0 = qbase + wid * 16 + g;
    const int row1 = row0 + 8;
    const int nkc = (qbase + 128) / 32;

    for (int kc = 0; kc < nkc; kc++) {
        int kbase = kc * 32;
        __syncthreads();   // sKV free (prev PV reads done / Q load done)

        // Load K chunk [32][64], hi/lo, SW128
        {
            int r = tid >> 3, c8 = tid & 7;
            const float* src = Kb + (size_t)(kbase + r) * DD + c8 * 8;
            float4 u = *(const float4*)src;
            float4 v = *(const float4*)(src + 4);
            float vals[8] = {u.x, u.y, u.z, u.w, v.x, v.y, v.z, v.w};
            uint4 hi, lo;
            split8(vals, hi, lo);
            uint32_t off = (uint32_t)(r * 128 + c8 * 16);
            off ^= (off >> 3) & 0x70;
            *(uint4*)(sKV + off) = hi;
            *(uint4*)(sKV + 4096 + off) = lo;
        }
        __syncthreads();

        // S = Q K^T (3-pass hi/lo), 128x32 tile, warp rows wid*16..+15
        float sc[4][4];
#pragma unroll
        for (int nj = 0; nj < 4; nj++)
#pragma unroll
            for (int r = 0; r < 4; r++) sc[nj][r] = 0.f;

#pragma unroll
        for (int kt = 0; kt < 4; kt++) {
            uint32_t ah[4], al[4], bh[8], bl[8];
            {
                uint32_t off = (uint32_t)((wid * 16 + (q & 1) * 8 + lr) * 128
                                          + (kt * 16 + (q >> 1) * 8) * 2);
                off ^= (off >> 3) & 0x70;
                ldm_x4(ah, uQh + off);
                ldm_x4(al, uQl + off);
            }
#pragma unroll
            for (int pj = 0; pj < 2; pj++) {
                uint32_t off = (uint32_t)((pj * 16 + (q >> 1) * 8 + lr) * 128
                                          + (kt * 16 + (q & 1) * 8) * 2);
                off ^= (off >> 3) & 0x70;
                ldm_x4(&bh[pj * 4], uKV + off);
                ldm_x4(&bl[pj * 4], uKV + 4096 + off);
            }
#pragma unroll
            for (int nj = 0; nj < 4; nj++) {
                mma16816(sc[nj], ah, &bh[nj * 2]);
                mma16816(sc[nj], ah, &bl[nj * 2]);
                mma16816(sc[nj], al, &bh[nj * 2]);
            }
        }

        // Causal mask + online softmax (registers; quad = one row)
        float mn0 = m0, mn1 = m1;
#pragma unroll
        for (int nj = 0; nj < 4; nj++) {
            int c0 = kbase + nj * 8 + tg * 2, c1 = c0 + 1;
            if (c0 > row0) sc[nj][0] = -1e30f;
            if (c1 > row0) sc[nj][1] = -1e30f;
            if (c0 > row1) sc[nj][2] = -1e30f;
            if (c1 > row1) sc[nj][3] = -1e30f;
            mn0 = fmaxf(mn0, fmaxf(sc[nj][0], sc[nj][1]));
            mn1 = fmaxf(mn1, fmaxf(sc[nj][2], sc[nj][3]));
        }
        mn0 = fmaxf(mn0, __shfl_xor_sync(0xFFFFFFFF, mn0, 1));
        mn0 = fmaxf(mn0, __shfl_xor_sync(0xFFFFFFFF, mn0, 2));
        mn1 = fmaxf(mn1, __shfl_xor_sync(0xFFFFFFFF, mn1, 1));
        mn1 = fmaxf(mn1, __shfl_xor_sync(0xFFFFFFFF, mn1, 2));

        float a0 = __expf(m0 - mn0), a1 = __expf(m1 - mn1);
        float rs0 = 0.f, rs1 = 0.f;
#pragma unroll
        for (int nj = 0; nj < 4; nj++) {
            sc[nj][0] = __expf(sc[nj][0] - mn0);
            sc[nj][1] = __expf(sc[nj][1] - mn0);
            sc[nj][2] = __expf(sc[nj][2] - mn1);
            sc[nj][3] = __expf(sc[nj][3] - mn1);
            rs0 += sc[nj][0] + sc[nj][1];
            rs1 += sc[nj][2] + sc[nj][3];
        }
        rs0 += __shfl_xor_sync(0xFFFFFFFF, rs0, 1);
        rs0 += __shfl_xor_sync(0xFFFFFFFF, rs0, 2);
        rs1 += __shfl_xor_sync(0xFFFFFFFF, rs1, 1);
        rs1 += __shfl_xor_sync(0xFFFFFFFF, rs1, 2);
        lsum0 = lsum0 * a0 + rs0;
        lsum1 = lsum1 * a1 + rs1;
        m0 = mn0; m1 = mn1;
#pragma unroll
        for (int d8 = 0; d8 < 8; d8++) {
            o[d8][0] *= a0; o[d8][1] *= a0;
            o[d8][2] *= a1; o[d8][3] *= a1;
        }

        __syncthreads();   // all warps done reading K fragments

        // Load V chunk transposed: [64 d][32 k] bf16, stride 40, hi/lo
        {
            int kq = tid & 31, db = (tid >> 5) * 8;
            const float* src = Vb + (size_t)(kbase + kq) * DD + db;
            float4 u = *(const float4*)src;
            float4 v = *(const float4*)(src + 4);
            float vals[8] = {u.x, u.y, u.z, u.w, v.x, v.y, v.z, v.w};
            __nv_bfloat16* vh = (__nv_bfloat16*)sKV;
            __nv_bfloat16* vl = (__nv_bfloat16*)(sKV + 5120);
#pragma unroll
            for (int i = 0; i < 8; i++) {
                __nv_bfloat16 hb = __float2bfloat16(vals[i]);
                vh[(db + i) * BSTR + kq] = hb;
                vl[(db + i) * BSTR + kq] =
                    __float2bfloat16(vals[i] - __bfloat162float(hb));
            }
        }
        __syncthreads();

        // P fragments from S C-frags (layout match), hi/lo split
        uint32_t ph[2][4], pl[2][4];
#pragma unroll
        for (int s = 0; s < 2; s++) {
#pragma unroll
            for (int half = 0; half < 2; half++) {   // ntiles 2s, 2s+1
                int nt = 2 * s + half;
                float p0 = sc[nt][0], p1 = sc[nt][1];
                float p2 = sc[nt][2], p3 = sc[nt][3];
                uint32_t h01 = pk_bf2(p0, p1), h23 = pk_bf2(p2, p3);
                __nv_bfloat162 hb01 = *reinterpret_cast<__nv_bfloat162*>(&h01);
                __nv_bfloat162 hb23 = *reinterpret_cast<__nv_bfloat162*>(&h23);
                ph[s][half * 2 + 0] = h01;
                ph[s][half * 2 + 1] = h23;
                pl[s][half * 2 + 0] = pk_bf2(p0 - __bfloat162float(hb01.x),
                                             p1 - __bfloat162float(hb01.y));
                pl[s][half * 2 + 1] = pk_bf2(p2 - __bfloat162float(hb23.x),
                                             p3 - __bfloat162float(hb23.y));
            }
        }
        // regs: ph[s] = {a0(nt 2s),a1(nt 2s),a2(nt 2s+1),a3(nt 2s+1)} but
        // A-frag order is {row g k0, row g+8 k0, row g k8, row g+8 k8}:
        // half=0 gives (c0,c1)=row g and (c2,c3)=row g+8 of k-low tile -> a0,a1;
        // half=1 -> k-high tile -> a2,a3.  Matches loop above. ✓

        // O += P V (3-pass hi/lo)
#pragma unroll
        for (int s = 0; s < 2; s++) {
#pragma unroll
            for (int pj = 0; pj < 4; pj++) {
                uint32_t vhf[4], vlf[4];
                uint32_t off = (uint32_t)((pj * 16 + (q >> 1) * 8 + lr) * BSTR
                                          + (s * 16 + (q & 1) * 8)) * 2;
                ldm_x4(vhf, uKV + off);
                ldm_x4(vlf, uKV + 5120 + off);
                mma16816(o[pj * 2],     ph[s], &vhf[0]);
                mma16816(o[pj * 2 + 1], ph[s], &vhf[2]);
                mma16816(o[pj * 2],     ph[s], &vlf[0]);
                mma16816(o[pj * 2 + 1], ph[s], &vlf[2]);
                mma16816(o[pj * 2],     pl[s], &vhf[0]);
                mma16816(o[pj * 2 + 1], pl[s], &vhf[2]);
            }
        }
    }

    // Epilogue: normalize and store head slice
    float i0 = 1.0f / lsum0, i1 = 1.0f / lsum1;
    float* Ob = O + (size_t)b * SS * DD + h * DKK;
#pragma unroll
    for (int d8 = 0; d8 < 8; d8++) {
        int col = d8 * 8 + tg * 2;
        *(float2*)(Ob + (size_t)row0 * DD + col) =
            make_float2(o[d8][0] * i0, o[d8][1] * i0);
        *(float2*)(Ob + (size_t)row1 * DD + col) =
            make_float2(o[d8][2] * i1, o[d8][3] * i1);
    }
}

// ---------------------------------------------------------------------------
// Launch
// ---------------------------------------------------------------------------
extern "C" void kernel_launch(void* const* d_in, const int* in_sizes, int n_in,
                              void* d_out, int out_size)
{
    const float* q  = (const float*)d_in[0];
    const float* k  = (const float*)d_in[1];
    const float* v  = (const float*)d_in[2];
    const float* Wq = (const float*)d_in[3];
    const float* bq = (const float*)d_in[4];
    const float* Wk = (const float*)d_in[5];
    const float* bk = (const float*)d_in[6];
    const float* Wv = (const float*)d_in[7];
    const float* bv = (const float*)d_in[8];
    const float* Wo = (const float*)d_in[9];
    const float* bo = (const float*)d_in[10];
    float* out = (float*)d_out;

    float *gq, *gk, *gv, *ga;
    __nv_bfloat16 *ah, *al, *wh, *wl;
    cudaGetSymbolAddress((void**)&gq, g_q);
    cudaGetSymbolAddress((void**)&gk, g_k);
    cudaGetSymbolAddress((void**)&gv, g_v);
    cudaGetSymbolAddress((void**)&ga, g_att);
    cudaGetSymbolAddress((void**)&ah, g_ah);
    cudaGetSymbolAddress((void**)&al, g_al);
    cudaGetSymbolAddress((void**)&wh, g_wh);
    cudaGetSymbolAddress((void**)&wl, g_wl);

    const int nA4 = MM * DD / 4;
    const int nW4 = DD * DD / 4;
    dim3 tcg(DD / 128, MM / 128);

    // Q projection
    cvt_hilo<<<nA4 / 256, 256>>>(q, ah, al, nA4);
    cvt_hilo<<<nW4 / 256, 256>>>(Wq, wh, wl, nW4);
    gemm_mma<<<tcg, 256>>>(ah, al, wh, wl, bq, gq);
    // K projection
    cvt_hilo<<<nA4 / 256, 256>>>(k, ah, al, nA4);
    cvt_hilo<<<nW4 / 256, 256>>>(Wk, wh, wl, nW4);
    gemm_mma<<<tcg, 256>>>(ah, al, wh, wl, bk, gk);
    // V projection
    cvt_hilo<<<nA4 / 256, 256>>>(v, ah, al, nA4);
    cvt_hilo<<<nW4 / 256, 256>>>(Wv, wh, wl, nW4);
    gemm_mma<<<tcg, 256>>>(ah, al, wh, wl, bv, gv);

    // Attention (tensor-core flash attention)
    attn_mma<<<dim3(SS / 128, HH, BB), 256>>>(gq, gk, gv, ga);

    // Output projection
    cvt_hilo<<<nA4 / 256, 256>>>(ga, ah, al, nA4);
    cvt_hilo<<<nW4 / 256, 256>>>(Wo, wh, wl, nW4);
    gemm_mma<<<tcg, 256>>>(ah, al, wh, wl, bo, out);
}

// round 14
// speedup vs baseline: 3.1357x; 1.0609x over previous
#include <cuda_runtime.h>
#include <cuda_bf16.h>
#include <math.h>
#include <stdint.h>

// Problem constants
#define BB   2
#define SS   2048
#define DD   1024
#define HH   16
#define DKK  64
#define MM   (BB*SS)   // 4096

// Scratch buffers (device globals — no allocation allowed)
__device__ float g_q[MM*DD];
__device__ float g_k[MM*DD];
__device__ float g_v[MM*DD];
__device__ float g_att[MM*DD];

// ---------------------------------------------------------------------------
// PTX helpers
// ---------------------------------------------------------------------------
__device__ __forceinline__ uint32_t smem_u32(const void* p) {
    uint32_t a;
    asm("{ .reg .u64 t; cvta.to.shared.u64 t, %1; cvt.u32.u64 %0, t; }"
        : "=r"(a) : "l"(p));
    return a;
}

__device__ __forceinline__ void ldm_x4(uint32_t* r, uint32_t addr) {
    asm volatile("ldmatrix.sync.aligned.m8n8.x4.shared.b16 {%0,%1,%2,%3}, [%4];"
                 : "=r"(r[0]), "=r"(r[1]), "=r"(r[2]), "=r"(r[3]) : "r"(addr));
}

__device__ __forceinline__ void mma16816(float* c, const uint32_t* a,
                                         const uint32_t* b) {
    asm volatile(
        "mma.sync.aligned.m16n8k16.row.col.f32.bf16.bf16.f32 "
        "{%0,%1,%2,%3}, {%4,%5,%6,%7}, {%8,%9}, {%0,%1,%2,%3};"
        : "+f"(c[0]), "+f"(c[1]), "+f"(c[2]), "+f"(c[3])
        : "r"(a[0]), "r"(a[1]), "r"(a[2]), "r"(a[3]), "r"(b[0]), "r"(b[1]));
}

__device__ __forceinline__ uint32_t pk_bf2(float a, float b) {
    __nv_bfloat162 t = __floats2bfloat162_rn(a, b);
    return *reinterpret_cast<uint32_t*>(&t);
}

// split 8 floats into bf16-hi uint4 and bf16-lo uint4
__device__ __forceinline__ void split8(const float* v, uint4& hi, uint4& lo) {
    uint32_t h[4], l[4];
#pragma unroll
    for (int i = 0; i < 4; i++) {
        float a = v[2*i], b = v[2*i+1];
        __nv_bfloat162 hb = __floats2bfloat162_rn(a, b);
        h[i] = *reinterpret_cast<uint32_t*>(&hb);
        float ra = a - __bfloat162float(hb.x);
        float rb = b - __bfloat162float(hb.y);
        __nv_bfloat162 lb = __floats2bfloat162_rn(ra, rb);
        l[i] = *reinterpret_cast<uint32_t*>(&lb);
    }
    hi = make_uint4(h[0], h[1], h[2], h[3]);
    lo = make_uint4(l[0], l[1], l[2], l[3]);
}

// ---------------------------------------------------------------------------
// Fused mma.sync bf16 hi/lo GEMM: C[M,N] = A[M,K] @ B[N,K]^T + bias.
// fp32 inputs split to (hi,lo) bf16 in the loader (same LDG bytes as bf16x2).
// C = Ah*Bh + Ah*Bl + Al*Bh. CTA tile 128x128, BK=32, 8 warps.
// ---------------------------------------------------------------------------
#define GBK  32
#define GNT  (DD / GBK)
#define BSTR 40

__device__ __forceinline__ void gemm_body(
    const float* __restrict__ A, const float* __restrict__ B,
    const float* __restrict__ bias, float* __restrict__ C,
    int bm, int bn,
    __nv_bfloat16* sAh, __nv_bfloat16* sAl,
    __nv_bfloat16* sBh, __nv_bfloat16* sBl)
{
    int tid = threadIdx.x;
    int wid = tid >> 5, lane = tid & 31;
    int wm = wid >> 2;
    int wn = wid & 3;

    uint32_t uAh = smem_u32(sAh), uAl = smem_u32(sAl);
    uint32_t uBh = smem_u32(sBh), uBl = smem_u32(sBl);

    float acc[4][4][4];
#pragma unroll
    for (int mi = 0; mi < 4; mi++)
#pragma unroll
        for (int nj = 0; nj < 4; nj++)
#pragma unroll
            for (int r = 0; r < 4; r++) acc[mi][nj][r] = 0.f;

    // fp32 prefetch: 2 slots x (A 8 floats + B 8 floats)
    float4 pA[4], pB[4];
    int ldrow0 = tid >> 2, ldc0 = (tid & 3);     // slot0 rows 0..63; slot1 +64

    auto ldg_chunk = [&](int t) {
        int k0 = t * GBK;
        const float* a0 = A + (size_t)(bm + ldrow0) * DD + k0 + ldc0 * 8;
        const float* b0 = B + (size_t)(bn + ldrow0) * DD + k0 + ldc0 * 8;
        pA[0] = *(const float4*)a0;
        pA[1] = *(const float4*)(a0 + 4);
        pB[0] = *(const float4*)b0;
        pB[1] = *(const float4*)(b0 + 4);
        const float* a1 = a0 + (size_t)64 * DD;
        const float* b1 = b0 + (size_t)64 * DD;
        pA[2] = *(const float4*)a1;
        pA[3] = *(const float4*)(a1 + 4);
        pB[2] = *(const float4*)b1;
        pB[3] = *(const float4*)(b1 + 4);
    };
    auto sts_chunk = [&]() {
        uint4 hi, lo;
        float va0[8] = {pA[0].x, pA[0].y, pA[0].z, pA[0].w,
                        pA[1].x, pA[1].y, pA[1].z, pA[1].w};
        split8(va0, hi, lo);
        *(uint4*)(sAh + ldrow0 * BSTR + ldc0 * 8) = hi;
        *(uint4*)(sAl + ldrow0 * BSTR + ldc0 * 8) = lo;
        float vb0[8] = {pB[0].x, pB[0].y, pB[0].z, pB[0].w,
                        pB[1].x, pB[1].y, pB[1].z, pB[1].w};
        split8(vb0, hi, lo);
        *(uint4*)(sBh + ldrow0 * BSTR + ldc0 * 8) = hi;
        *(uint4*)(sBl + ldrow0 * BSTR + ldc0 * 8) = lo;
        float va1[8] = {pA[2].x, pA[2].y, pA[2].z, pA[2].w,
                        pA[3].x, pA[3].y, pA[3].z, pA[3].w};
        split8(va1, hi, lo);
        *(uint4*)(sAh + (ldrow0 + 64) * BSTR + ldc0 * 8) = hi;
        *(uint4*)(sAl + (ldrow0 + 64) * BSTR + ldc0 * 8) = lo;
        float vb1[8] = {pB[2].x, pB[2].y, pB[2].z, pB[2].w,
                        pB[3].x, pB[3].y, pB[3].z, pB[3].w};
        split8(vb1, hi, lo);
        *(uint4*)(sBh + (ldrow0 + 64) * BSTR + ldc0 * 8) = hi;
        *(uint4*)(sBl + (ldrow0 + 64) * BSTR + ldc0 * 8) = lo;
    };

    int q = lane >> 3;
    int lr = lane & 7;

    ldg_chunk(0);
    for (int t = 0; t < GNT; t++) {
        sts_chunk();
        __syncthreads();
        if (t + 1 < GNT) ldg_chunk(t + 1);

#pragma unroll
        for (int kk = 0; kk < 2; kk++) {
            uint32_t ah[16], al[16], bh[8], bl[8];
            {
                int arow = wm * 64 + (q & 1) * 8 + lr;
                int akof = kk * 16 + (q >> 1) * 8;
                uint32_t off = (uint32_t)(arow * BSTR + akof) * 2;
#pragma unroll
                for (int mi = 0; mi < 4; mi++) {
                    ldm_x4(&ah[mi * 4], uAh + off + mi * 16 * BSTR * 2);
                    ldm_x4(&al[mi * 4], uAl + off + mi * 16 * BSTR * 2);
                }
            }
            {
                int brow = wn * 32 + (q >> 1) * 8 + lr;
                int bkof = kk * 16 + (q & 1) * 8;
                uint32_t off = (uint32_t)(brow * BSTR + bkof) * 2;
#pragma unroll
                for (int pj = 0; pj < 2; pj++) {
                    ldm_x4(&bh[pj * 4], uBh + off + pj * 16 * BSTR * 2);
                    ldm_x4(&bl[pj * 4], uBl + off + pj * 16 * BSTR * 2);
                }
            }
#pragma unroll
            for (int mi = 0; mi < 4; mi++)
#pragma unroll
                for (int nj = 0; nj < 4; nj++) {
                    mma16816(acc[mi][nj], &ah[mi * 4], &bh[nj * 2]);
                    mma16816(acc[mi][nj], &ah[mi * 4], &bl[nj * 2]);
                    mma16816(acc[mi][nj], &al[mi * 4], &bh[nj * 2]);
                }
        }
        __syncthreads();
    }

    int g = lane >> 2, tg = lane & 3;
#pragma unroll
    for (int mi = 0; mi < 4; mi++) {
#pragma unroll
        for (int nj = 0; nj < 4; nj++) {
            int row = bm + wm * 64 + mi * 16 + g;
            int col = bn + wn * 32 + nj * 8 + tg * 2;
            float b0 = bias[col], b1 = bias[col + 1];
            float2 v0 = make_float2(acc[mi][nj][0] + b0, acc[mi][nj][1] + b1);
            float2 v1 = make_float2(acc[mi][nj][2] + b0, acc[mi][nj][3] + b1);
            *(float2*)(C + (size_t)row * DD + col) = v0;
            *(float2*)(C + (size_t)(row + 8) * DD + col) = v1;
        }
    }
}

// Merged Q/K/V projection: grid (8, 32, 3), z selects matrix set.
__global__ __launch_bounds__(256, 1) void qkv_gemm(
    const float* __restrict__ Aq, const float* __restrict__ Ak,
    const float* __restrict__ Av,
    const float* __restrict__ Wq, const float* __restrict__ Wk,
    const float* __restrict__ Wv,
    const float* __restrict__ bq, const float* __restrict__ bk,
    const float* __restrict__ bv,
    float* __restrict__ Cq, float* __restrict__ Ck, float* __restrict__ Cv)
{
    __shared__ __align__(16) __nv_bfloat16 sAh[128 * BSTR];
    __shared__ __align__(16) __nv_bfloat16 sAl[128 * BSTR];
    __shared__ __align__(16) __nv_bfloat16 sBh[128 * BSTR];
    __shared__ __align__(16) __nv_bfloat16 sBl[128 * BSTR];
    int z = blockIdx.z;
    const float* A = (z == 0) ? Aq : (z == 1) ? Ak : Av;
    const float* W = (z == 0) ? Wq : (z == 1) ? Wk : Wv;
    const float* bi = (z == 0) ? bq : (z == 1) ? bk : bv;
    float* C = (z == 0) ? Cq : (z == 1) ? Ck : Cv;
    gemm_body(A, W, bi, C, blockIdx.y * 128, blockIdx.x * 128,
              sAh, sAl, sBh, sBl);
}

// Single fused GEMM (output projection).
__global__ __launch_bounds__(256, 1) void out_gemm(
    const float* __restrict__ A, const float* __restrict__ W,
    const float* __restrict__ bias, float* __restrict__ C)
{
    __shared__ __align__(16) __nv_bfloat16 sAh[128 * BSTR];
    __shared__ __align__(16) __nv_bfloat16 sAl[128 * BSTR];
    __shared__ __align__(16) __nv_bfloat16 sBh[128 * BSTR];
    __shared__ __align__(16) __nv_bfloat16 sBl[128 * BSTR];
    gemm_body(A, W, bias, C, blockIdx.y * 128, blockIdx.x * 128,
              sAh, sAl, sBh, sBl);
}

// ---------------------------------------------------------------------------
// Flash attention with mma.sync bf16 (hi/lo, 3-pass), register online softmax.
// Unchanged from round 9 (verified, ~245us).
// ---------------------------------------------------------------------------
__global__ __launch_bounds__(256, 1) void attn_mma(
    const float* __restrict__ Q, const float* __restrict__ K,
    const float* __restrict__ V, float* __restrict__ O)
{
    __shared__ __align__(16) __nv_bfloat16 sQh[128 * 64];
    __shared__ __align__(16) __nv_bfloat16 sQl[128 * 64];
    __shared__ __align__(16) char sKV[10240];

    int tid = threadIdx.x;
    int wid = tid >> 5, lane = tid & 31;
    int g = lane >> 2, tg = lane & 3;
    int q = lane >> 3, lr = lane & 7;
    int qblk = (int)gridDim.x - 1 - (int)blockIdx.x;
    int h = blockIdx.y, b = blockIdx.z;
    int qbase = qblk * 128;

    const float* Qb = Q + (size_t)b * SS * DD + h * DKK;
    const float* Kb = K + (size_t)b * SS * DD + h * DKK;
    const float* Vb = V + (size_t)b * SS * DD + h * DKK;

    uint32_t uQh = smem_u32(sQh), uQl = smem_u32(sQl);
    uint32_t uKV = smem_u32(sKV);

#pragma unroll
    for (int it = 0; it < 4; it++) {
        int slot = tid + it * 256;
        int r = slot >> 3, c8 = slot & 7;
        const float* src = Qb + (size_t)(qbase + r) * DD + c8 * 8;
        float4 u = *(const float4*)src;
        float4 v = *(const float4*)(src + 4);
        float vals[8] = {u.x*0.125f, u.y*0.125f, u.z*0.125f, u.w*0.125f,
                         v.x*0.125f, v.y*0.125f, v.z*0.125f, v.w*0.125f};
        uint4 hi, lo;
        split8(vals, hi, lo);
        uint32_t off = (uint32_t)(r * 128 + c8 * 16);
        off ^= (off >> 3) & 0x70;
        *(uint4*)((char*)sQh + off) = hi;
        *(uint4*)((char*)sQl + off) = lo;
    }

    float m0 = -1e30f, m1 = -1e30f, lsum0 = 0.f, lsum1 = 0.f;
    float o[8][4];
#pragma unroll
    for (int d8 = 0; d8 < 8; d8++)
#pragma unroll
        for (int r = 0; r < 4; r++) o[d8][r] = 0.f;

    const int row0 = qbase + wid * 16 + g;
    const int row1 = row0 + 8;
    const int nkc = (qbase + 128) / 32;

    for (int kc = 0; kc < nkc; kc++) {
        int kbase = kc * 32;
        __syncthreads();

        {
            int r = tid >> 3, c8 = tid & 7;
            const float* src = Kb + (size_t)(kbase + r) * DD + c8 * 8;
            float4 u = *(const float4*)src;
            float4 v = *(const float4*)(src + 4);
            float vals[8] = {u.x, u.y, u.z, u.w, v.x, v.y, v.z, v.w};
            uint4 hi, lo;
            split8(vals, hi, lo);
            uint32_t off = (uint32_t)(r * 128 + c8 * 16);
            off ^= (off >> 3) & 0x70;
            *(uint4*)(sKV + off) = hi;
            *(uint4*)(sKV + 4096 + off) = lo;
        }
        __syncthreads();

        float sc[4][4];
#pragma unroll
        for (int nj = 0; nj < 4; nj++)
#pragma unroll
            for (int r = 0; r < 4; r++) sc[nj][r] = 0.f;

#pragma unroll
        for (int kt = 0; kt < 4; kt++) {
            uint32_t ah[4], al[4], bh[8], bl[8];
            {
                uint32_t off = (uint32_t)((wid * 16 + (q & 1) * 8 + lr) * 128
                                          + (kt * 16 + (q >> 1) * 8) * 2);
                off ^= (off >> 3) & 0x70;
                ldm_x4(ah, uQh + off);
                ldm_x4(al, uQl + off);
            }
#pragma unroll
            for (int pj = 0; pj < 2; pj++) {
                uint32_t off = (uint32_t)((pj * 16 + (q >> 1) * 8 + lr) * 128
                                          + (kt * 16 + (q & 1) * 8) * 2);
                off ^= (off >> 3) & 0x70;
                ldm_x4(&bh[pj * 4], uKV + off);
                ldm_x4(&bl[pj * 4], uKV + 4096 + off);
            }
#pragma unroll
            for (int nj = 0; nj < 4; nj++) {
                mma16816(sc[nj], ah, &bh[nj * 2]);
                mma16816(sc[nj], ah, &bl[nj * 2]);
                mma16816(sc[nj], al, &bh[nj * 2]);
            }
        }

        float mn0 = m0, mn1 = m1;
#pragma unroll
        for (int nj = 0; nj < 4; nj++) {
            int c0 = kbase + nj * 8 + tg * 2, c1 = c0 + 1;
            if (c0 > row0) sc[nj][0] = -1e30f;
            if (c1 > row0) sc[nj][1] = -1e30f;
            if (c0 > row1) sc[nj][2] = -1e30f;
            if (c1 > row1) sc[nj][3] = -1e30f;
            mn0 = fmaxf(mn0, fmaxf(sc[nj][0], sc[nj][1]));
            mn1 = fmaxf(mn1, fmaxf(sc[nj][2], sc[nj][3]));
        }
        mn0 = fmaxf(mn0, __shfl_xor_sync(0xFFFFFFFF, mn0, 1));
        mn0 = fmaxf(mn0, __shfl_xor_sync(0xFFFFFFFF, mn0, 2));
        mn1 = fmaxf(mn1, __shfl_xor_sync(0xFFFFFFFF, mn1, 1));
        mn1 = fmaxf(mn1, __shfl_xor_sync(0xFFFFFFFF, mn1, 2));

        float a0 = __expf(m0 - mn0), a1 = __expf(m1 - mn1);
        float rs0 = 0.f, rs1 = 0.f;
#pragma unroll
        for (int nj = 0; nj < 4; nj++) {
            sc[nj][0] = __expf(sc[nj][0] - mn0);
            sc[nj][1] = __expf(sc[nj][1] - mn0);
            sc[nj][2] = __expf(sc[nj][2] - mn1);
            sc[nj][3] = __expf(sc[nj][3] - mn1);
            rs0 += sc[nj][0] + sc[nj][1];
            rs1 += sc[nj][2] + sc[nj][3];
        }
        rs0 += __shfl_xor_sync(0xFFFFFFFF, rs0, 1);
        rs0 += __shfl_xor_sync(0xFFFFFFFF, rs0, 2);
        rs1 += __shfl_xor_sync(0xFFFFFFFF, rs1, 1);
        rs1 += __shfl_xor_sync(0xFFFFFFFF, rs1, 2);
        lsum0 = lsum0 * a0 + rs0;
        lsum1 = lsum1 * a1 + rs1;
        m0 = mn0; m1 = mn1;
#pragma unroll
        for (int d8 = 0; d8 < 8; d8++) {
            o[d8][0] *= a0; o[d8][1] *= a0;
            o[d8][2] *= a1; o[d8][3] *= a1;
        }

        __syncthreads();

        {
            int kq = tid & 31, db = (tid >> 5) * 8;
            const float* src = Vb + (size_t)(kbase + kq) * DD + db;
            float4 u = *(const float4*)src;
            float4 v = *(const float4*)(src + 4);
            float vals[8] = {u.x, u.y, u.z, u.w, v.x, v.y, v.z, v.w};
            __nv_bfloat16* vh = (__nv_bfloat16*)sKV;
            __nv_bfloat16* vl = (__nv_bfloat16*)(sKV + 5120);
#pragma unroll
            for (int i = 0; i < 8; i++) {
                __nv_bfloat16 hb = __float2bfloat16(vals[i]);
                vh[(db + i) * BSTR + kq] = hb;
                vl[(db + i) * BSTR + kq] =
                    __float2bfloat16(vals[i] - __bfloat162float(hb));
            }
        }
        __syncthreads();

        uint32_t ph[2][4], pl[2][4];
#pragma unroll
        for (int s = 0; s < 2; s++) {
#pragma unroll
            for (int half = 0; half < 2; half++) {
                int nt = 2 * s + half;
                float p0 = sc[nt][0], p1 = sc[nt][1];
                float p2 = sc[nt][2], p3 = sc[nt][3];
                uint32_t h01 = pk_bf2(p0, p1), h23 = pk_bf2(p2, p3);
                __nv_bfloat162 hb01 = *reinterpret_cast<__nv_bfloat162*>(&h01);
                __nv_bfloat162 hb23 = *reinterpret_cast<__nv_bfloat162*>(&h23);
                ph[s][half * 2 + 0] = h01;
                ph[s][half * 2 + 1] = h23;
                pl[s][half * 2 + 0] = pk_bf2(p0 - __bfloat162float(hb01.x),
                                             p1 - __bfloat162float(hb01.y));
                pl[s][half * 2 + 1] = pk_bf2(p2 - __bfloat162float(hb23.x),
                                             p3 - __bfloat162float(hb23.y));
            }
        }

#pragma unroll
        for (int s = 0; s < 2; s++) {
#pragma unroll
            for (int pj = 0; pj < 4; pj++) {
                uint32_t vhf[4], vlf[4];
                uint32_t off = (uint32_t)((pj * 16 + (q >> 1) * 8 + lr) * BSTR
                                          + (s * 16 + (q & 1) * 8)) * 2;
                ldm_x4(vhf, uKV + off);
                ldm_x4(vlf, uKV + 5120 + off);
                mma16816(o[pj * 2],     ph[s], &vhf[0]);
                mma16816(o[pj * 2 + 1], ph[s], &vhf[2]);
                mma16816(o[pj * 2],     ph[s], &vlf[0]);
                mma16816(o[pj * 2 + 1], ph[s], &vlf[2]);
                mma16816(o[pj * 2],     pl[s], &vhf[0]);
                mma16816(o[pj * 2 + 1], pl[s], &vhf[2]);
            }
        }
    }

    float i0 = 1.0f / lsum0, i1 = 1.0f / lsum1;
    float* Ob = O + (size_t)b * SS * DD + h * DKK;
#pragma unroll
    for (int d8 = 0; d8 < 8; d8++) {
        int col = d8 * 8 + tg * 2;
        *(float2*)(Ob + (size_t)row0 * DD + col) =
            make_float2(o[d8][0] * i0, o[d8][1] * i0);
        *(float2*)(Ob + (size_t)row1 * DD + col) =
            make_float2(o[d8][2] * i1, o[d8][3] * i1);
    }
}

// ---------------------------------------------------------------------------
// Launch
// ---------------------------------------------------------------------------
extern "C" void kernel_launch(void* const* d_in, const int* in_sizes, int n_in,
                              void* d_out, int out_size)
{
    (void)in_sizes; (void)n_in; (void)out_size;
    const float* q  = (const float*)d_in[0];
    const float* k  = (const float*)d_in[1];
    const float* v  = (const float*)d_in[2];
    const float* Wq = (const float*)d_in[3];
    const float* bq = (const float*)d_in[4];
    const float* Wk = (const float*)d_in[5];
    const float* bk = (const float*)d_in[6];
    const float* Wv = (const float*)d_in[7];
    const float* bv = (const float*)d_in[8];
    const float* Wo = (const float*)d_in[9];
    const float* bo = (const float*)d_in[10];
    float* out = (float*)d_out;

    float *gq, *gk, *gv, *ga;
    cudaGetSymbolAddress((void**)&gq, g_q);
    cudaGetSymbolAddress((void**)&gk, g_k);
    cudaGetSymbolAddress((void**)&gv, g_v);
    cudaGetSymbolAddress((void**)&ga, g_att);

    // Q/K/V projections in one launch (grid.z selects matrix set)
    qkv_gemm<<<dim3(DD / 128, MM / 128, 3), 256>>>(
        q, k, v, Wq, Wk, Wv, bq, bk, bv, gq, gk, gv);

    // Tensor-core flash attention
    attn_mma<<<dim3(SS / 128, HH, BB), 256>>>(gq, gk, gv, ga);

    // Output projection
    out_gemm<<<dim3(DD / 128, MM / 128), 256>>>(ga, Wo, bo, out);
}

// round 15
// speedup vs baseline: 3.1699x; 1.0109x over previous
#include <cuda_runtime.h>
#include <cuda_bf16.h>
#include <math.h>
#include <stdint.h>

// Problem constants
#define BB   2
#define SS   2048
#define DD   1024
#define HH   16
#define DKK  64
#define MM   (BB*SS)   // 4096

// Scratch buffers (device globals — no allocation allowed)
__device__ float g_q[MM*DD];
__device__ float g_k[MM*DD];
__device__ float g_v[MM*DD];
__device__ float g_att[MM*DD];

// ---------------------------------------------------------------------------
// PTX helpers
// ---------------------------------------------------------------------------
__device__ __forceinline__ uint32_t smem_u32(const void* p) {
    uint32_t a;
    asm("{ .reg .u64 t; cvta.to.shared.u64 t, %1; cvt.u32.u64 %0, t; }"
        : "=r"(a) : "l"(p));
    return a;
}

__device__ __forceinline__ void ldm_x4(uint32_t* r, uint32_t addr) {
    asm volatile("ldmatrix.sync.aligned.m8n8.x4.shared.b16 {%0,%1,%2,%3}, [%4];"
                 : "=r"(r[0]), "=r"(r[1]), "=r"(r[2]), "=r"(r[3]) : "r"(addr));
}

__device__ __forceinline__ void mma16816(float* c, const uint32_t* a,
                                         const uint32_t* b) {
    asm volatile(
        "mma.sync.aligned.m16n8k16.row.col.f32.bf16.bf16.f32 "
        "{%0,%1,%2,%3}, {%4,%5,%6,%7}, {%8,%9}, {%0,%1,%2,%3};"
        : "+f"(c[0]), "+f"(c[1]), "+f"(c[2]), "+f"(c[3])
        : "r"(a[0]), "r"(a[1]), "r"(a[2]), "r"(a[3]), "r"(b[0]), "r"(b[1]));
}

__device__ __forceinline__ uint32_t pk_bf2(float a, float b) {
    __nv_bfloat162 t = __floats2bfloat162_rn(a, b);
    return *reinterpret_cast<uint32_t*>(&t);
}

// split 8 floats into bf16-hi uint4 and bf16-lo uint4
__device__ __forceinline__ void split8(const float* v, uint4& hi, uint4& lo) {
    uint32_t h[4], l[4];
#pragma unroll
    for (int i = 0; i < 4; i++) {
        float a = v[2*i], b = v[2*i+1];
        __nv_bfloat162 hb = __floats2bfloat162_rn(a, b);
        h[i] = *reinterpret_cast<uint32_t*>(&hb);
        float ra = a - __bfloat162float(hb.x);
        float rb = b - __bfloat162float(hb.y);
        __nv_bfloat162 lb = __floats2bfloat162_rn(ra, rb);
        l[i] = *reinterpret_cast<uint32_t*>(&lb);
    }
    hi = make_uint4(h[0], h[1], h[2], h[3]);
    lo = make_uint4(l[0], l[1], l[2], l[3]);
}

// ---------------------------------------------------------------------------
// GEMM v2: C[M,N] = A[M,K] @ B[N,K]^T + bias, fused fp32->bf16 hi/lo split.
// CTA tile 128(M) x 256(N), BK=16, 8 warps (2m x 4n), warp tile 64x64.
// Smem row stride 24 elems (48B) -> LDSM row banks (3i mod 8) distinct.
// Per stage/warp: 12 LDSM.x4 vs 96 MMA (ratio 6; was 4).
// ---------------------------------------------------------------------------
#define GBK2  16
#define GNT2  (DD / GBK2)   // 64 stages
#define BST2  24            // elems per smem row (48 bytes)

__device__ __forceinline__ void gemm_body2(
    const float* __restrict__ A, const float* __restrict__ B,
    const float* __restrict__ bias, float* __restrict__ C,
    int bm, int bn,
    __nv_bfloat16* sAh, __nv_bfloat16* sAl,
    __nv_bfloat16* sBh, __nv_bfloat16* sBl)
{
    int tid = threadIdx.x;
    int wid = tid >> 5, lane = tid & 31;
    int wm = wid >> 2;        // 0..1 -> m offset wm*64
    int wn = wid & 3;         // 0..3 -> n offset wn*64
    int q = lane >> 3, lr = lane & 7;

    uint32_t uAh = smem_u32(sAh), uAl = smem_u32(sAl);
    uint32_t uBh = smem_u32(sBh), uBl = smem_u32(sBl);

    float acc[4][8][4];
#pragma unroll
    for (int mi = 0; mi < 4; mi++)
#pragma unroll
        for (int nj = 0; nj < 8; nj++)
#pragma unroll
            for (int r = 0; r < 4; r++) acc[mi][nj][r] = 0.f;

    // Loader: per thread 3 rows x 8 floats: A row r0, B rows r0, r0+128.
    int r0 = tid >> 1, cg = (tid & 1) * 8;
    float4 pf[6];

    auto ldg_chunk = [&](int t) {
        int k0 = t * GBK2;
        const float* pa  = A + (size_t)(bm + r0) * DD + k0 + cg;
        const float* pb0 = B + (size_t)(bn + r0) * DD + k0 + cg;
        const float* pb1 = pb0 + (size_t)128 * DD;
        pf[0] = *(const float4*)pa;
        pf[1] = *(const float4*)(pa + 4);
        pf[2] = *(const float4*)pb0;
        pf[3] = *(const float4*)(pb0 + 4);
        pf[4] = *(const float4*)pb1;
        pf[5] = *(const float4*)(pb1 + 4);
    };
    auto sts_chunk = [&]() {
        uint4 hi, lo;
        float va[8] = {pf[0].x, pf[0].y, pf[0].z, pf[0].w,
                       pf[1].x, pf[1].y, pf[1].z, pf[1].w};
        split8(va, hi, lo);
        *(uint4*)(sAh + r0 * BST2 + cg) = hi;
        *(uint4*)(sAl + r0 * BST2 + cg) = lo;
        float vb0[8] = {pf[2].x, pf[2].y, pf[2].z, pf[2].w,
                        pf[3].x, pf[3].y, pf[3].z, pf[3].w};
        split8(vb0, hi, lo);
        *(uint4*)(sBh + r0 * BST2 + cg) = hi;
        *(uint4*)(sBl + r0 * BST2 + cg) = lo;
        float vb1[8] = {pf[4].x, pf[4].y, pf[4].z, pf[4].w,
                        pf[5].x, pf[5].y, pf[5].z, pf[5].w};
        split8(vb1, hi, lo);
        *(uint4*)(sBh + (r0 + 128) * BST2 + cg) = hi;
        *(uint4*)(sBl + (r0 + 128) * BST2 + cg) = lo;
    };

    ldg_chunk(0);
    for (int t = 0; t < GNT2; t++) {
        sts_chunk();
        __syncthreads();
        if (t + 1 < GNT2) ldg_chunk(t + 1);

        // B fragments: 4 x4-loads (hi) + 4 (lo), covering 8 n-tiles
        uint32_t bh[16], bl[16];
        {
            int brow = wn * 64 + (q >> 1) * 8 + lr;
            int bkof = (q & 1) * 8;
            uint32_t off = (uint32_t)(brow * BST2 + bkof) * 2;
#pragma unroll
            for (int pj = 0; pj < 4; pj++) {
                ldm_x4(&bh[pj * 4], uBh + off + pj * 16 * BST2 * 2);
                ldm_x4(&bl[pj * 4], uBl + off + pj * 16 * BST2 * 2);
            }
        }
        // A fragments loaded per mi (keeps regs low; ptxas pipelines across mi)
        {
            int arow = wm * 64 + (q & 1) * 8 + lr;
            int akof = (q >> 1) * 8;
            uint32_t offA = (uint32_t)(arow * BST2 + akof) * 2;
#pragma unroll
            for (int mi = 0; mi < 4; mi++) {
                uint32_t ah[4], al[4];
                ldm_x4(ah, uAh + offA + mi * 16 * BST2 * 2);
                ldm_x4(al, uAl + offA + mi * 16 * BST2 * 2);
#pragma unroll
                for (int nj = 0; nj < 8; nj++) {
                    mma16816(acc[mi][nj], ah, &bh[nj * 2]);
                    mma16816(acc[mi][nj], ah, &bl[nj * 2]);
                    mma16816(acc[mi][nj], al, &bh[nj * 2]);
                }
            }
        }
        __syncthreads();
    }

    int g = lane >> 2, tg = lane & 3;
#pragma unroll
    for (int mi = 0; mi < 4; mi++) {
#pragma unroll
        for (int nj = 0; nj < 8; nj++) {
            int row = bm + wm * 64 + mi * 16 + g;
            int col = bn + wn * 64 + nj * 8 + tg * 2;
            float b0 = bias[col], b1 = bias[col + 1];
            float2 v0 = make_float2(acc[mi][nj][0] + b0, acc[mi][nj][1] + b1);
            float2 v1 = make_float2(acc[mi][nj][2] + b0, acc[mi][nj][3] + b1);
            *(float2*)(C + (size_t)row * DD + col) = v0;
            *(float2*)(C + (size_t)(row + 8) * DD + col) = v1;
        }
    }
}

// Merged Q/K/V projection: grid (1024/256, 4096/128, 3).
__global__ __launch_bounds__(256, 1) void qkv_gemm(
    const float* __restrict__ Aq, const float* __restrict__ Ak,
    const float* __restrict__ Av,
    const float* __restrict__ Wq, const float* __restrict__ Wk,
    const float* __restrict__ Wv,
    const float* __restrict__ bq, const float* __restrict__ bk,
    const float* __restrict__ bv,
    float* __restrict__ Cq, float* __restrict__ Ck, float* __restrict__ Cv)
{
    __shared__ __align__(16) __nv_bfloat16 sAh[128 * BST2];
    __shared__ __align__(16) __nv_bfloat16 sAl[128 * BST2];
    __shared__ __align__(16) __nv_bfloat16 sBh[256 * BST2];
    __shared__ __align__(16) __nv_bfloat16 sBl[256 * BST2];
    int z = blockIdx.z;
    const float* A = (z == 0) ? Aq : (z == 1) ? Ak : Av;
    const float* W = (z == 0) ? Wq : (z == 1) ? Wk : Wv;
    const float* bi = (z == 0) ? bq : (z == 1) ? bk : bv;
    float* C = (z == 0) ? Cq : (z == 1) ? Ck : Cv;
    gemm_body2(A, W, bi, C, blockIdx.y * 128, blockIdx.x * 256,
               sAh, sAl, sBh, sBl);
}

// Output projection.
__global__ __launch_bounds__(256, 1) void out_gemm(
    const float* __restrict__ A, const float* __restrict__ W,
    const float* __restrict__ bias, float* __restrict__ C)
{
    __shared__ __align__(16) __nv_bfloat16 sAh[128 * BST2];
    __shared__ __align__(16) __nv_bfloat16 sAl[128 * BST2];
    __shared__ __align__(16) __nv_bfloat16 sBh[256 * BST2];
    __shared__ __align__(16) __nv_bfloat16 sBl[256 * BST2];
    gemm_body2(A, W, bias, C, blockIdx.y * 128, blockIdx.x * 256,
               sAh, sAl, sBh, sBl);
}

// ---------------------------------------------------------------------------
// Flash attention with mma.sync bf16 (hi/lo, 3-pass), register online softmax.
// Unchanged (verified, ~245us).
// ---------------------------------------------------------------------------
#define BSTR 40

__global__ __launch_bounds__(256, 1) void attn_mma(
    const float* __restrict__ Q, const float* __restrict__ K,
    const float* __restrict__ V, float* __restrict__ O)
{
    __shared__ __align__(16) __nv_bfloat16 sQh[128 * 64];
    __shared__ __align__(16) __nv_bfloat16 sQl[128 * 64];
    __shared__ __align__(16) char sKV[10240];

    int tid = threadIdx.x;
    int wid = tid >> 5, lane = tid & 31;
    int g = lane >> 2, tg = lane & 3;
    int q = lane >> 3, lr = lane & 7;
    int qblk = (int)gridDim.x - 1 - (int)blockIdx.x;
    int h = blockIdx.y, b = blockIdx.z;
    int qbase = qblk * 128;

    const float* Qb = Q + (size_t)b * SS * DD + h * DKK;
    const float* Kb = K + (size_t)b * SS * DD + h * DKK;
    const float* Vb = V + (size_t)b * SS * DD + h * DKK;

    uint32_t uQh = smem_u32(sQh), uQl = smem_u32(sQl);
    uint32_t uKV = smem_u32(sKV);

#pragma unroll
    for (int it = 0; it < 4; it++) {
        int slot = tid + it * 256;
        int r = slot >> 3, c8 = slot & 7;
        const float* src = Qb + (size_t)(qbase + r) * DD + c8 * 8;
        float4 u = *(const float4*)src;
        float4 v = *(const float4*)(src + 4);
        float vals[8] = {u.x*0.125f, u.y*0.125f, u.z*0.125f, u.w*0.125f,
                         v.x*0.125f, v.y*0.125f, v.z*0.125f, v.w*0.125f};
        uint4 hi, lo;
        split8(vals, hi, lo);
        uint32_t off = (uint32_t)(r * 128 + c8 * 16);
        off ^= (off >> 3) & 0x70;
        *(uint4*)((char*)sQh + off) = hi;
        *(uint4*)((char*)sQl + off) = lo;
    }

    float m0 = -1e30f, m1 = -1e30f, lsum0 = 0.f, lsum1 = 0.f;
    float o[8][4];
#pragma unroll
    for (int d8 = 0; d8 < 8; d8++)
#pragma unroll
        for (int r = 0; r < 4; r++) o[d8][r] = 0.f;

    const int row0 = qbase + wid * 16 + g;
    const int row1 = row0 + 8;
    const int nkc = (qbase + 128) / 32;

    for (int kc = 0; kc < nkc; kc++) {
        int kbase = kc * 32;
        __syncthreads();

        {
            int r = tid >> 3, c8 = tid & 7;
            const float* src = Kb + (size_t)(kbase + r) * DD + c8 * 8;
            float4 u = *(const float4*)src;
            float4 v = *(const float4*)(src + 4);
            float vals[8] = {u.x, u.y, u.z, u.w, v.x, v.y, v.z, v.w};
            uint4 hi, lo;
            split8(vals, hi, lo);
            uint32_t off = (uint32_t)(r * 128 + c8 * 16);
            off ^= (off >> 3) & 0x70;
            *(uint4*)(sKV + off) = hi;
            *(uint4*)(sKV + 4096 + off) = lo;
        }
        __syncthreads();

        float sc[4][4];
#pragma unroll
        for (int nj = 0; nj < 4; nj++)
#pragma unroll
            for (int r = 0; r < 4; r++) sc[nj][r] = 0.f;

#pragma unroll
        for (int kt = 0; kt < 4; kt++) {
            uint32_t ah[4], al[4], bh[8], bl[8];
            {
                uint32_t off = (uint32_t)((wid * 16 + (q & 1) * 8 + lr) * 128
                                          + (kt * 16 + (q >> 1) * 8) * 2);
                off ^= (off >> 3) & 0x70;
                ldm_x4(ah, uQh + off);
                ldm_x4(al, uQl + off);
            }
#pragma unroll
            for (int pj = 0; pj < 2; pj++) {
                uint32_t off = (uint32_t)((pj * 16 + (q >> 1) * 8 + lr) * 128
                                          + (kt * 16 + (q & 1) * 8) * 2);
                off ^= (off >> 3) & 0x70;
                ldm_x4(&bh[pj * 4], uKV + off);
                ldm_x4(&bl[pj * 4], uKV + 4096 + off);
            }
#pragma unroll
            for (int nj = 0; nj < 4; nj++) {
                mma16816(sc[nj], ah, &bh[nj * 2]);
                mma16816(sc[nj], ah, &bl[nj * 2]);
                mma16816(sc[nj], al, &bh[nj * 2]);
            }
        }

        float mn0 = m0, mn1 = m1;
#pragma unroll
        for (int nj = 0; nj < 4; nj++) {
            int c0 = kbase + nj * 8 + tg * 2, c1 = c0 + 1;
            if (c0 > row0) sc[nj][0] = -1e30f;
            if (c1 > row0) sc[nj][1] = -1e30f;
            if (c0 > row1) sc[nj][2] = -1e30f;
            if (c1 > row1) sc[nj][3] = -1e30f;
            mn0 = fmaxf(mn0, fmaxf(sc[nj][0], sc[nj][1]));
            mn1 = fmaxf(mn1, fmaxf(sc[nj][2], sc[nj][3]));
        }
        mn0 = fmaxf(mn0, __shfl_xor_sync(0xFFFFFFFF, mn0, 1));
        mn0 = fmaxf(mn0, __shfl_xor_sync(0xFFFFFFFF, mn0, 2));
        mn1 = fmaxf(mn1, __shfl_xor_sync(0xFFFFFFFF, mn1, 1));
        mn1 = fmaxf(mn1, __shfl_xor_sync(0xFFFFFFFF, mn1, 2));

        float a0 = __expf(m0 - mn0), a1 = __expf(m1 - mn1);
        float rs0 = 0.f, rs1 = 0.f;
#pragma unroll
        for (int nj = 0; nj < 4; nj++) {
            sc[nj][0] = __expf(sc[nj][0] - mn0);
            sc[nj][1] = __expf(sc[nj][1] - mn0);
            sc[nj][2] = __expf(sc[nj][2] - mn1);
            sc[nj][3] = __expf(sc[nj][3] - mn1);
            rs0 += sc[nj][0] + sc[nj][1];
            rs1 += sc[nj][2] + sc[nj][3];
        }
        rs0 += __shfl_xor_sync(0xFFFFFFFF, rs0, 1);
        rs0 += __shfl_xor_sync(0xFFFFFFFF, rs0, 2);
        rs1 += __shfl_xor_sync(0xFFFFFFFF, rs1, 1);
        rs1 += __shfl_xor_sync(0xFFFFFFFF, rs1, 2);
        lsum0 = lsum0 * a0 + rs0;
        lsum1 = lsum1 * a1 + rs1;
        m0 = mn0; m1 = mn1;
#pragma unroll
        for (int d8 = 0; d8 < 8; d8++) {
            o[d8][0] *= a0; o[d8][1] *= a0;
            o[d8][2] *= a1; o[d8][3] *= a1;
        }

        __syncthreads();

        {
            int kq = tid & 31, db = (tid >> 5) * 8;
            const float* src = Vb + (size_t)(kbase + kq) * DD + db;
            float4 u = *(const float4*)src;
            float4 v = *(const float4*)(src + 4);
            float vals[8] = {u.x, u.y, u.z, u.w, v.x, v.y, v.z, v.w};
            __nv_bfloat16* vh = (__nv_bfloat16*)sKV;
            __nv_bfloat16* vl = (__nv_bfloat16*)(sKV + 5120);
#pragma unroll
            for (int i = 0; i < 8; i++) {
                __nv_bfloat16 hb = __float2bfloat16(vals[i]);
                vh[(db + i) * BSTR + kq] = hb;
                vl[(db + i) * BSTR + kq] =
                    __float2bfloat16(vals[i] - __bfloat162float(hb));
            }
        }
        __syncthreads();

        uint32_t ph[2][4], pl[2][4];
#pragma unroll
        for (int s = 0; s < 2; s++) {
#pragma unroll
            for (int half = 0; half < 2; half++) {
                int nt = 2 * s + half;
                float p0 = sc[nt][0], p1 = sc[nt][1];
                float p2 = sc[nt][2], p3 = sc[nt][3];
                uint32_t h01 = pk_bf2(p0, p1), h23 = pk_bf2(p2, p3);
                __nv_bfloat162 hb01 = *reinterpret_cast<__nv_bfloat162*>(&h01);
                __nv_bfloat162 hb23 = *reinterpret_cast<__nv_bfloat162*>(&h23);
                ph[s][half * 2 + 0] = h01;
                ph[s][half * 2 + 1] = h23;
                pl[s][half * 2 + 0] = pk_bf2(p0 - __bfloat162float(hb01.x),
                                             p1 - __bfloat162float(hb01.y));
                pl[s][half * 2 + 1] = pk_bf2(p2 - __bfloat162float(hb23.x),
                                             p3 - __bfloat162float(hb23.y));
            }
        }

#pragma unroll
        for (int s = 0; s < 2; s++) {
#pragma unroll
            for (int pj = 0; pj < 4; pj++) {
                uint32_t vhf[4], vlf[4];
                uint32_t off = (uint32_t)((pj * 16 + (q >> 1) * 8 + lr) * BSTR
                                          + (s * 16 + (q & 1) * 8)) * 2;
                ldm_x4(vhf, uKV + off);
                ldm_x4(vlf, uKV + 5120 + off);
                mma16816(o[pj * 2],     ph[s], &vhf[0]);
                mma16816(o[pj * 2 + 1], ph[s], &vhf[2]);
                mma16816(o[pj * 2],     ph[s], &vlf[0]);
                mma16816(o[pj * 2 + 1], ph[s], &vlf[2]);
                mma16816(o[pj * 2],     pl[s], &vhf[0]);
                mma16816(o[pj * 2 + 1], pl[s], &vhf[2]);
            }
        }
    }

    float i0 = 1.0f / lsum0, i1 = 1.0f / lsum1;
    float* Ob = O + (size_t)b * SS * DD + h * DKK;
#pragma unroll
    for (int d8 = 0; d8 < 8; d8++) {
        int col = d8 * 8 + tg * 2;
        *(float2*)(Ob + (size_t)row0 * DD + col) =
            make_float2(o[d8][0] * i0, o[d8][1] * i0);
        *(float2*)(Ob + (size_t)row1 * DD + col) =
            make_float2(o[d8][2] * i1, o[d8][3] * i1);
    }
}

// ---------------------------------------------------------------------------
// Launch
// ---------------------------------------------------------------------------
extern "C" void kernel_launch(void* const* d_in, const int* in_sizes, int n_in,
                              void* d_out, int out_size)
{
    (void)in_sizes; (void)n_in; (void)out_size;
    const float* q  = (const float*)d_in[0];
    const float* k  = (const float*)d_in[1];
    const float* v  = (const float*)d_in[2];
    const float* Wq = (const float*)d_in[3];
    const float* bq = (const float*)d_in[4];
    const float* Wk = (const float*)d_in[5];
    const float* bk = (const float*)d_in[6];
    const float* Wv = (const float*)d_in[7];
    const float* bv = (const float*)d_in[8];
    const float* Wo = (const float*)d_in[9];
    const float* bo = (const float*)d_in[10];
    float* out = (float*)d_out;

    float *gq, *gk, *gv, *ga;
    cudaGetSymbolAddress((void**)&gq, g_q);
    cudaGetSymbolAddress((void**)&gk, g_k);
    cudaGetSymbolAddress((void**)&gv, g_v);
    cudaGetSymbolAddress((void**)&ga, g_att);

    // Q/K/V projections in one launch (grid.z selects matrix set)
    qkv_gemm<<<dim3(DD / 256, MM / 128, 3), 256>>>(
        q, k, v, Wq, Wk, Wv, bq, bk, bv, gq, gk, gv);

    // Tensor-core flash attention
    attn_mma<<<dim3(SS / 128, HH, BB), 256>>>(gq, gk, gv, ga);

    // Output projection
    out_gemm<<<dim3(DD / 256, MM / 128), 256>>>(ga, Wo, bo, out);
}

// round 17
// speedup vs baseline: 3.2601x; 1.0285x over previous
#include <cuda_runtime.h>
#include <cuda_bf16.h>
#include <math.h>
#include <stdint.h>

// Problem constants
#define BB   2
#define SS   2048
#define DD   1024
#define HH   16
#define DKK  64
#define MM   (BB*SS)   // 4096

// Scratch buffers (device globals — no allocation allowed)
__device__ float g_q[MM*DD];
__device__ float g_k[MM*DD];
__device__ float g_v[MM*DD];
__device__ float g_att[MM*DD];

// ---------------------------------------------------------------------------
// PTX helpers
// ---------------------------------------------------------------------------
__device__ __forceinline__ uint32_t smem_u32(const void* p) {
    uint32_t a;
    asm("{ .reg .u64 t; cvta.to.shared.u64 t, %1; cvt.u32.u64 %0, t; }"
        : "=r"(a) : "l"(p));
    return a;
}

__device__ __forceinline__ void ldm_x4(uint32_t* r, uint32_t addr) {
    asm volatile("ldmatrix.sync.aligned.m8n8.x4.shared.b16 {%0,%1,%2,%3}, [%4];"
                 : "=r"(r[0]), "=r"(r[1]), "=r"(r[2]), "=r"(r[3]) : "r"(addr));
}

__device__ __forceinline__ void mma16816(float* c, const uint32_t* a,
                                         const uint32_t* b) {
    asm volatile(
        "mma.sync.aligned.m16n8k16.row.col.f32.bf16.bf16.f32 "
        "{%0,%1,%2,%3}, {%4,%5,%6,%7}, {%8,%9}, {%0,%1,%2,%3};"
        : "+f"(c[0]), "+f"(c[1]), "+f"(c[2]), "+f"(c[3])
        : "r"(a[0]), "r"(a[1]), "r"(a[2]), "r"(a[3]), "r"(b[0]), "r"(b[1]));
}

__device__ __forceinline__ uint32_t pk_bf2(float a, float b) {
    __nv_bfloat162 t = __floats2bfloat162_rn(a, b);
    return *reinterpret_cast<uint32_t*>(&t);
}

// split 8 floats into bf16-hi uint4 and bf16-lo uint4
__device__ __forceinline__ void split8(const float* v, uint4& hi, uint4& lo) {
    uint32_t h[4], l[4];
#pragma unroll
    for (int i = 0; i < 4; i++) {
        float a = v[2*i], b = v[2*i+1];
        __nv_bfloat162 hb = __floats2bfloat162_rn(a, b);
        h[i] = *reinterpret_cast<uint32_t*>(&hb);
        float ra = a - __bfloat162float(hb.x);
        float rb = b - __bfloat162float(hb.y);
        __nv_bfloat162 lb = __floats2bfloat162_rn(ra, rb);
        l[i] = *reinterpret_cast<uint32_t*>(&lb);
    }
    hi = make_uint4(h[0], h[1], h[2], h[3]);
    lo = make_uint4(l[0], l[1], l[2], l[3]);
}

// ---------------------------------------------------------------------------
// GEMM v2 (round-15 verified): C[M,N] = A[M,K] @ B[N,K]^T + bias.
// CTA tile 128(M) x 256(N), BK=16, 8 warps (2m x 4n), warp tile 64x64.
// ---------------------------------------------------------------------------
#define GBK2  16
#define GNT2  (DD / GBK2)   // 64 stages
#define BST2  24            // elems per smem row (48 bytes)

__device__ __forceinline__ void gemm_body2(
    const float* __restrict__ A, const float* __restrict__ B,
    const float* __restrict__ bias, float* __restrict__ C,
    int bm, int bn,
    __nv_bfloat16* sAh, __nv_bfloat16* sAl,
    __nv_bfloat16* sBh, __nv_bfloat16* sBl)
{
    int tid = threadIdx.x;
    int wid = tid >> 5, lane = tid & 31;
    int wm = wid >> 2;
    int wn = wid & 3;
    int q = lane >> 3, lr = lane & 7;

    uint32_t uAh = smem_u32(sAh), uAl = smem_u32(sAl);
    uint32_t uBh = smem_u32(sBh), uBl = smem_u32(sBl);

    float acc[4][8][4];
#pragma unroll
    for (int mi = 0; mi < 4; mi++)
#pragma unroll
        for (int nj = 0; nj < 8; nj++)
#pragma unroll
            for (int r = 0; r < 4; r++) acc[mi][nj][r] = 0.f;

    int r0 = tid >> 1, cg = (tid & 1) * 8;
    float4 pf[6];

    auto ldg_chunk = [&](int t) {
        int k0 = t * GBK2;
        const float* pa  = A + (size_t)(bm + r0) * DD + k0 + cg;
        const float* pb0 = B + (size_t)(bn + r0) * DD + k0 + cg;
        const float* pb1 = pb0 + (size_t)128 * DD;
        pf[0] = *(const float4*)pa;
        pf[1] = *(const float4*)(pa + 4);
        pf[2] = *(const float4*)pb0;
        pf[3] = *(const float4*)(pb0 + 4);
        pf[4] = *(const float4*)pb1;
        pf[5] = *(const float4*)(pb1 + 4);
    };
    auto sts_chunk = [&]() {
        uint4 hi, lo;
        float va[8] = {pf[0].x, pf[0].y, pf[0].z, pf[0].w,
                       pf[1].x, pf[1].y, pf[1].z, pf[1].w};
        split8(va, hi, lo);
        *(uint4*)(sAh + r0 * BST2 + cg) = hi;
        *(uint4*)(sAl + r0 * BST2 + cg) = lo;
        float vb0[8] = {pf[2].x, pf[2].y, pf[2].z, pf[2].w,
                        pf[3].x, pf[3].y, pf[3].z, pf[3].w};
        split8(vb0, hi, lo);
        *(uint4*)(sBh + r0 * BST2 + cg) = hi;
        *(uint4*)(sBl + r0 * BST2 + cg) = lo;
        float vb1[8] = {pf[4].x, pf[4].y, pf[4].z, pf[4].w,
                        pf[5].x, pf[5].y, pf[5].z, pf[5].w};
        split8(vb1, hi, lo);
        *(uint4*)(sBh + (r0 + 128) * BST2 + cg) = hi;
        *(uint4*)(sBl + (r0 + 128) * BST2 + cg) = lo;
    };

    ldg_chunk(0);
    for (int t = 0; t < GNT2; t++) {
        sts_chunk();
        __syncthreads();
        if (t + 1 < GNT2) ldg_chunk(t + 1);

        uint32_t bh[16], bl[16];
        {
            int brow = wn * 64 + (q >> 1) * 8 + lr;
            int bkof = (q & 1) * 8;
            uint32_t off = (uint32_t)(brow * BST2 + bkof) * 2;
#pragma unroll
            for (int pj = 0; pj < 4; pj++) {
                ldm_x4(&bh[pj * 4], uBh + off + pj * 16 * BST2 * 2);
                ldm_x4(&bl[pj * 4], uBl + off + pj * 16 * BST2 * 2);
            }
        }
        {
            int arow = wm * 64 + (q & 1) * 8 + lr;
            int akof = (q >> 1) * 8;
            uint32_t offA = (uint32_t)(arow * BST2 + akof) * 2;
#pragma unroll
            for (int mi = 0; mi < 4; mi++) {
                uint32_t ah[4], al[4];
                ldm_x4(ah, uAh + offA + mi * 16 * BST2 * 2);
                ldm_x4(al, uAl + offA + mi * 16 * BST2 * 2);
#pragma unroll
                for (int nj = 0; nj < 8; nj++) {
                    mma16816(acc[mi][nj], ah, &bh[nj * 2]);
                    mma16816(acc[mi][nj], ah, &bl[nj * 2]);
                    mma16816(acc[mi][nj], al, &bh[nj * 2]);
                }
            }
        }
        __syncthreads();
    }

    int g = lane >> 2, tg = lane & 3;
#pragma unroll
    for (int mi = 0; mi < 4; mi++) {
#pragma unroll
        for (int nj = 0; nj < 8; nj++) {
            int row = bm + wm * 64 + mi * 16 + g;
            int col = bn + wn * 64 + nj * 8 + tg * 2;
            float b0 = bias[col], b1 = bias[col + 1];
            float2 v0 = make_float2(acc[mi][nj][0] + b0, acc[mi][nj][1] + b1);
            float2 v1 = make_float2(acc[mi][nj][2] + b0, acc[mi][nj][3] + b1);
            *(float2*)(C + (size_t)row * DD + col) = v0;
            *(float2*)(C + (size_t)(row + 8) * DD + col) = v1;
        }
    }
}

// Merged Q/K/V projection: grid (4, 32, 3).
__global__ __launch_bounds__(256, 1) void qkv_gemm(
    const float* __restrict__ Aq, const float* __restrict__ Ak,
    const float* __restrict__ Av,
    const float* __restrict__ Wq, const float* __restrict__ Wk,
    const float* __restrict__ Wv,
    const float* __restrict__ bq, const float* __restrict__ bk,
    const float* __restrict__ bv,
    float* __restrict__ Cq, float* __restrict__ Ck, float* __restrict__ Cv)
{
    __shared__ __align__(16) __nv_bfloat16 sAh[128 * BST2];
    __shared__ __align__(16) __nv_bfloat16 sAl[128 * BST2];
    __shared__ __align__(16) __nv_bfloat16 sBh[256 * BST2];
    __shared__ __align__(16) __nv_bfloat16 sBl[256 * BST2];
    int z = blockIdx.z;
    const float* A = (z == 0) ? Aq : (z == 1) ? Ak : Av;
    const float* W = (z == 0) ? Wq : (z == 1) ? Wk : Wv;
    const float* bi = (z == 0) ? bq : (z == 1) ? bk : bv;
    float* C = (z == 0) ? Cq : (z == 1) ? Ck : Cv;
    gemm_body2(A, W, bi, C, blockIdx.y * 128, blockIdx.x * 256,
               sAh, sAl, sBh, sBl);
}

// Output projection.
__global__ __launch_bounds__(256, 1) void out_gemm(
    const float* __restrict__ A, const float* __restrict__ W,
    const float* __restrict__ bias, float* __restrict__ C)
{
    __shared__ __align__(16) __nv_bfloat16 sAh[128 * BST2];
    __shared__ __align__(16) __nv_bfloat16 sAl[128 * BST2];
    __shared__ __align__(16) __nv_bfloat16 sBh[256 * BST2];
    __shared__ __align__(16) __nv_bfloat16 sBl[256 * BST2];
    gemm_body2(A, W, bias, C, blockIdx.y * 128, blockIdx.x * 256,
               sAh, sAl, sBh, sBl);
}

// ---------------------------------------------------------------------------
// Flash attention, mma.sync bf16 hi/lo 3-pass, register online softmax.
// v2: separate K and V smem buffers -> both loaded up front per chunk,
// 2 syncthreads/chunk (was 4); 2 CTAs/SM for phase overlap.
// ---------------------------------------------------------------------------
#define BSTR 40

__global__ __launch_bounds__(256, 2) void attn_mma(
    const float* __restrict__ Q, const float* __restrict__ K,
    const float* __restrict__ V, float* __restrict__ O)
{
    __shared__ __align__(16) __nv_bfloat16 sQh[128 * 64];   // 16 KB
    __shared__ __align__(16) __nv_bfloat16 sQl[128 * 64];   // 16 KB
    __shared__ __align__(16) char sK[8192];    // K hi@0, lo@4096 (SW128)
    __shared__ __align__(16) char sV[10240];   // V^T hi@0, lo@5120 (stride 40)

    int tid = threadIdx.x;
    int wid = tid >> 5, lane = tid & 31;
    int g = lane >> 2, tg = lane & 3;
    int q = lane >> 3, lr = lane & 7;
    int qblk = (int)gridDim.x - 1 - (int)blockIdx.x;   // heavy blocks first
    int h = blockIdx.y, b = blockIdx.z;
    int qbase = qblk * 128;

    const float* Qb = Q + (size_t)b * SS * DD + h * DKK;
    const float* Kb = K + (size_t)b * SS * DD + h * DKK;
    const float* Vb = V + (size_t)b * SS * DD + h * DKK;

    uint32_t uQh = smem_u32(sQh), uQl = smem_u32(sQl);
    uint32_t uK = smem_u32(sK), uV = smem_u32(sV);

    // Load Q tile (x 1/sqrt(dk)), hi/lo split, SW128
#pragma unroll
    for (int it = 0; it < 4; it++) {
        int slot = tid + it * 256;
        int r = slot >> 3, c8 = slot & 7;
        const float* src = Qb + (size_t)(qbase + r) * DD + c8 * 8;
        float4 u = *(const float4*)src;
        float4 v = *(const float4*)(src + 4);
        float vals[8] = {u.x*0.125f, u.y*0.125f, u.z*0.125f, u.w*0.125f,
                         v.x*0.125f, v.y*0.125f, v.z*0.125f, v.w*0.125f};
        uint4 hi, lo;
        split8(vals, hi, lo);
        uint32_t off = (uint32_t)(r * 128 + c8 * 16);
        off ^= (off >> 3) & 0x70;
        *(uint4*)((char*)sQh + off) = hi;
        *(uint4*)((char*)sQl + off) = lo;
    }

    float m0 = -1e30f, m1 = -1e30f, lsum0 = 0.f, lsum1 = 0.f;
    float o[8][4];
#pragma unroll
    for (int d8 = 0; d8 < 8; d8++)
#pragma unroll
        for (int r = 0; r < 4; r++) o[d8][r] = 0.f;

    const int row0 = qbase + wid * 16 + g;
    const int row1 = row0 + 8;
    const int nkc = (qbase + 128) / 32;

    for (int kc = 0; kc < nkc; kc++) {
        int kbase = kc * 32;
        __syncthreads();   // prior chunk's K/V fragment reads complete

        // Load K chunk [32][64], hi/lo, SW128
        {
            int r = tid >> 3, c8 = tid & 7;
            const float* src = Kb + (size_t)(kbase + r) * DD + c8 * 8;
            float4 u = *(const float4*)src;
            float4 v = *(const float4*)(src + 4);
            float vals[8] = {u.x, u.y, u.z, u.w, v.x, v.y, v.z, v.w};
            uint4 hi, lo;
            split8(vals, hi, lo);
            uint32_t off = (uint32_t)(r * 128 + c8 * 16);
            off ^= (off >> 3) & 0x70;
            *(uint4*)(sK + off) = hi;
            *(uint4*)(sK + 4096 + off) = lo;
        }
        // Load V chunk transposed [64 d][32 k], stride 40, hi/lo
        {
            int kq = tid & 31, db = (tid >> 5) * 8;
            const float* src = Vb + (size_t)(kbase + kq) * DD + db;
            float4 u = *(const float4*)src;
            float4 v = *(const float4*)(src + 4);
            float vals[8] = {u.x, u.y, u.z, u.w, v.x, v.y, v.z, v.w};
            __nv_bfloat16* vh = (__nv_bfloat16*)sV;
            __nv_bfloat16* vl = (__nv_bfloat16*)(sV + 5120);
#pragma unroll
            for (int i = 0; i < 8; i++) {
                __nv_bfloat16 hb = __float2bfloat16(vals[i]);
                vh[(db + i) * BSTR + kq] = hb;
                vl[(db + i) * BSTR + kq] =
                    __float2bfloat16(vals[i] - __bfloat162float(hb));
            }
        }
        __syncthreads();

        // S = Q K^T (3-pass hi/lo), 128x32 tile
        float sc[4][4];
#pragma unroll
        for (int nj = 0; nj < 4; nj++)
#pragma unroll
            for (int r = 0; r < 4; r++) sc[nj][r] = 0.f;

#pragma unroll
        for (int kt = 0; kt < 4; kt++) {
            uint32_t ah[4], al[4], bh[8], bl[8];
            {
                uint32_t off = (uint32_t)((wid * 16 + (q & 1) * 8 + lr) * 128
                                          + (kt * 16 + (q >> 1) * 8) * 2);
                off ^= (off >> 3) & 0x70;
                ldm_x4(ah, uQh + off);
                ldm_x4(al, uQl + off);
            }
#pragma unroll
            for (int pj = 0; pj < 2; pj++) {
                uint32_t off = (uint32_t)((pj * 16 + (q >> 1) * 8 + lr) * 128
                                          + (kt * 16 + (q & 1) * 8) * 2);
                off ^= (off >> 3) & 0x70;
                ldm_x4(&bh[pj * 4], uK + off);
                ldm_x4(&bl[pj * 4], uK + 4096 + off);
            }
#pragma unroll
            for (int nj = 0; nj < 4; nj++) {
                mma16816(sc[nj], ah, &bh[nj * 2]);
                mma16816(sc[nj], ah, &bl[nj * 2]);
                mma16816(sc[nj], al, &bh[nj * 2]);
            }
        }

        // Causal mask + online softmax (registers; quad = one row)
        float mn0 = m0, mn1 = m1;
#pragma unroll
        for (int nj = 0; nj < 4; nj++) {
            int c0 = kbase + nj * 8 + tg * 2, c1 = c0 + 1;
            if (c0 > row0) sc[nj][0] = -1e30f;
            if (c1 > row0) sc[nj][1] = -1e30f;
            if (c0 > row1) sc[nj][2] = -1e30f;
            if (c1 > row1) sc[nj][3] = -1e30f;
            mn0 = fmaxf(mn0, fmaxf(sc[nj][0], sc[nj][1]));
            mn1 = fmaxf(mn1, fmaxf(sc[nj][2], sc[nj][3]));
        }
        mn0 = fmaxf(mn0, __shfl_xor_sync(0xFFFFFFFF, mn0, 1));
        mn0 = fmaxf(mn0, __shfl_xor_sync(0xFFFFFFFF, mn0, 2));
        mn1 = fmaxf(mn1, __shfl_xor_sync(0xFFFFFFFF, mn1, 1));
        mn1 = fmaxf(mn1, __shfl_xor_sync(0xFFFFFFFF, mn1, 2));

        float a0 = __expf(m0 - mn0), a1 = __expf(m1 - mn1);
        float rs0 = 0.f, rs1 = 0.f;
#pragma unroll
        for (int nj = 0; nj < 4; nj++) {
            sc[nj][0] = __expf(sc[nj][0] - mn0);
            sc[nj][1] = __expf(sc[nj][1] - mn0);
            sc[nj][2] = __expf(sc[nj][2] - mn1);
            sc[nj][3] = __expf(sc[nj][3] - mn1);
            rs0 += sc[nj][0] + sc[nj][1];
            rs1 += sc[nj][2] + sc[nj][3];
        }
        rs0 += __shfl_xor_sync(0xFFFFFFFF, rs0, 1);
        rs0 += __shfl_xor_sync(0xFFFFFFFF, rs0, 2);
        rs1 += __shfl_xor_sync(0xFFFFFFFF, rs1, 1);
        rs1 += __shfl_xor_sync(0xFFFFFFFF, rs1, 2);
        lsum0 = lsum0 * a0 + rs0;
        lsum1 = lsum1 * a1 + rs1;
        m0 = mn0; m1 = mn1;
#pragma unroll
        for (int d8 = 0; d8 < 8; d8++) {
            o[d8][0] *= a0; o[d8][1] *= a0;
            o[d8][2] *= a1; o[d8][3] *= a1;
        }

        // P fragments from S C-frags (layout match), hi/lo split
        uint32_t ph[2][4], pl[2][4];
#pragma unroll
        for (int s = 0; s < 2; s++) {
#pragma unroll
            for (int half = 0; half < 2; half++) {
                int nt = 2 * s + half;
                float p0 = sc[nt][0], p1 = sc[nt][1];
                float p2 = sc[nt][2], p3 = sc[nt][3];
                uint32_t h01 = pk_bf2(p0, p1), h23 = pk_bf2(p2, p3);
                __nv_bfloat162 hb01 = *reinterpret_cast<__nv_bfloat162*>(&h01);
                __nv_bfloat162 hb23 = *reinterpret_cast<__nv_bfloat162*>(&h23);
                ph[s][half * 2 + 0] = h01;
                ph[s][half * 2 + 1] = h23;
                pl[s][half * 2 + 0] = pk_bf2(p0 - __bfloat162float(hb01.x),
                                             p1 - __bfloat162float(hb01.y));
                pl[s][half * 2 + 1] = pk_bf2(p2 - __bfloat162float(hb23.x),
                                             p3 - __bfloat162float(hb23.y));
            }
        }

        // O += P V (3-pass hi/lo); V already resident
#pragma unroll
        for (int s = 0; s < 2; s++) {
#pragma unroll
            for (int pj = 0; pj < 4; pj++) {
                uint32_t vhf[4], vlf[4];
                uint32_t off = (uint32_t)((pj * 16 + (q >> 1) * 8 + lr) * BSTR
                                          + (s * 16 + (q & 1) * 8)) * 2;
                ldm_x4(vhf, uV + off);
                ldm_x4(vlf, uV + 5120 + off);
                mma16816(o[pj * 2],     ph[s], &vhf[0]);
                mma16816(o[pj * 2 + 1], ph[s], &vhf[2]);
                mma16816(o[pj * 2],     ph[s], &vlf[0]);
                mma16816(o[pj * 2 + 1], ph[s], &vlf[2]);
                mma16816(o[pj * 2],     pl[s], &vhf[0]);
                mma16816(o[pj * 2 + 1], pl[s], &vhf[2]);
            }
        }
    }

    // Epilogue: normalize and store head slice
    float i0 = 1.0f / lsum0, i1 = 1.0f / lsum1;
    float* Ob = O + (size_t)b * SS * DD + h * DKK;
#pragma unroll
    for (int d8 = 0; d8 < 8; d8++) {
        int col = d8 * 8 + tg * 2;
        *(float2*)(Ob + (size_t)row0 * DD + col) =
            make_float2(o[d8][0] * i0, o[d8][1] * i0);
        *(float2*)(Ob + (size_t)row1 * DD + col) =
            make_float2(o[d8][2] * i1, o[d8][3] * i1);
    }
}

// ---------------------------------------------------------------------------
// Launch
// ---------------------------------------------------------------------------
extern "C" void kernel_launch(void* const* d_in, const int* in_sizes, int n_in,
                              void* d_out, int out_size)
{
    (void)in_sizes; (void)n_in; (void)out_size;
    const float* q  = (const float*)d_in[0];
    const float* k  = (const float*)d_in[1];
    const float* v  = (const float*)d_in[2];
    const float* Wq = (const float*)d_in[3];
    const float* bq = (const float*)d_in[4];
    const float* Wk = (const float*)d_in[5];
    const float* bk = (const float*)d_in[6];
    const float* Wv = (const float*)d_in[7];
    const float* bv = (const float*)d_in[8];
    const float* Wo = (const float*)d_in[9];
    const float* bo = (const float*)d_in[10];
    float* out = (float*)d_out;

    float *gq, *gk, *gv, *ga;
    cudaGetSymbolAddress((void**)&gq, g_q);
    cudaGetSymbolAddress((void**)&gk, g_k);
    cudaGetSymbolAddress((void**)&gv, g_v);
    cudaGetSymbolAddress((void**)&ga, g_att);

    // Q/K/V projections in one launch (grid.z selects matrix set)
    qkv_gemm<<<dim3(DD / 256, MM / 128, 3), 256>>>(
        q, k, v, Wq, Wk, Wv, bq, bk, bv, gq, gk, gv);

    // Tensor-core flash attention (2 CTAs/SM, 2 syncs/chunk)
    attn_mma<<<dim3(SS / 128, HH, BB), 256>>>(gq, gk, gv, ga);

    // Output projection
    out_gemm<<<dim3(DD / 256, MM / 128), 256>>>(ga, Wo, bo, out);
}